// round 1
// baseline (speedup 1.0000x reference)
#include <cuda_runtime.h>
#include <math.h>

// Problem dimensions (fixed by the reference)
#define NB   8
#define CC   1024
#define TT   16
#define HH   14
#define WW   14
#define DD   512
#define THW  (TT*HH*WW)   // 3136
#define PH   (HH/2)       // 7
#define PW   (WW/2)       // 7
#define PP   (TT*PH*PW)   // 784

// Scratch (static device globals; no allocations allowed)
__device__ float g_xp   [NB*CC*PP];    // pooled x          [N,C,P]
__device__ float g_theta[NB*DD*THW];   // theta             [N,D,THW]
__device__ float g_phi  [NB*DD*PP];    // phi               [N,D,P]
__device__ float g_gg   [NB*DD*PP];    // g                 [N,D,P]
__device__ float g_attn [NB*THW*PP];   // logits/attn       [N,THW,P]
__device__ float g_o    [NB*DD*THW];   // attn@g            [N,D,THW]

// ---------------------------------------------------------------------------
// Max pool (1,2,2) stride (1,2,2): [N,C,T,14,14] -> [N,C,T,7,7]
// ---------------------------------------------------------------------------
__global__ void pool_kernel(const float* __restrict__ x, float* __restrict__ xp,
                            int total) {
    int idx = blockIdx.x * blockDim.x + threadIdx.x;
    if (idx >= total) return;
    int j   = idx % PW;
    int tmp = idx / PW;
    int i   = tmp % PH;
    tmp /= PH;                       // tmp = (n*C + c)*T + t
    const float* base = x + (long long)tmp * (HH*WW) + (2*i)*WW + 2*j;
    float m = fmaxf(fmaxf(base[0], base[1]), fmaxf(base[WW], base[WW+1]));
    xp[idx] = m;
}

// ---------------------------------------------------------------------------
// Warp-per-row softmax over the last dim (cols = 784)
// ---------------------------------------------------------------------------
__global__ void softmax_kernel(float* __restrict__ data, int rows, int cols) {
    int warp = blockIdx.x * (blockDim.x >> 5) + (threadIdx.x >> 5);
    if (warp >= rows) return;
    int lane = threadIdx.x & 31;
    float* row = data + (long long)warp * cols;

    float vals[25];
    int cnt = 0;
    float mx = -INFINITY;
    for (int c = lane; c < cols; c += 32) {
        float v = row[c];
        vals[cnt++] = v;
        mx = fmaxf(mx, v);
    }
    #pragma unroll
    for (int o = 16; o; o >>= 1) mx = fmaxf(mx, __shfl_xor_sync(0xffffffffu, mx, o));
    float sum = 0.f;
    for (int i = 0; i < cnt; i++) {
        vals[i] = __expf(vals[i] - mx);
        sum += vals[i];
    }
    #pragma unroll
    for (int o = 16; o; o >>= 1) sum += __shfl_xor_sync(0xffffffffu, sum, o);
    float inv = 1.0f / sum;
    cnt = 0;
    for (int c = lane; c < cols; c += 32) row[c] = vals[cnt++] * inv;
}

// ---------------------------------------------------------------------------
// Templated batched SGEMM: C[bz] = alpha * opA(A[bz]) * opB(B[bz])
//   TA=false: A is [M,K] row-major (element A[m*K+k])
//   TA=true : A stored [K,M]      (element A[k*M+m])
//   TB=false: B is [K,N] row-major (element B[k*N+n])
//   TB=true : B stored [N,K]      (element B[n*K+k])
//   EPI=true: C = resid + (acc*scale[row] + bias[row])   (alpha ignored)
// 128x128 block tile, BK=8, 256 threads, 8x8 per-thread micro-tile.
// Requires: K % 8 == 0, M % 4 == 0, N % 4 == 0 (true for all uses here).
// ---------------------------------------------------------------------------
#define BM 128
#define BN 128
#define BK 8

template<bool TA, bool TB, bool EPI>
__global__ __launch_bounds__(256, 2)
void gemm_kernel(const float* __restrict__ A, const float* __restrict__ B,
                 float* __restrict__ C, int M, int N, int K,
                 long long sA, long long sB, long long sC, float alpha,
                 const float* __restrict__ scale, const float* __restrict__ bias,
                 const float* __restrict__ resid, long long sR) {
    __shared__ float As[BK][BM];
    __shared__ float Bs[BK][BN + 4];

    const int bz = blockIdx.z;
    A += (long long)bz * sA;
    B += (long long)bz * sB;
    C += (long long)bz * sC;

    const int bm = blockIdx.y * BM;
    const int bn = blockIdx.x * BN;
    const int tid = threadIdx.x;
    const int tx = tid & 15;    // column group (8 cols each)
    const int ty = tid >> 4;    // row group (8 rows each)

    float acc[8][8];
    #pragma unroll
    for (int i = 0; i < 8; i++)
        #pragma unroll
        for (int j = 0; j < 8; j++) acc[i][j] = 0.f;

    for (int k0 = 0; k0 < K; k0 += BK) {
        // ---- load A tile into As[k][m] ----
        if (!TA) {
            int m  = tid >> 1;
            int kk = (tid & 1) * 4;
            float4 v = make_float4(0.f, 0.f, 0.f, 0.f);
            if (bm + m < M)
                v = *reinterpret_cast<const float4*>(&A[(long long)(bm + m) * K + k0 + kk]);
            As[kk + 0][m] = v.x; As[kk + 1][m] = v.y;
            As[kk + 2][m] = v.z; As[kk + 3][m] = v.w;
        } else {
            int kk = tid >> 5;
            int m  = (tid & 31) * 4;
            float4 v = make_float4(0.f, 0.f, 0.f, 0.f);
            if (bm + m < M)
                v = *reinterpret_cast<const float4*>(&A[(long long)(k0 + kk) * M + bm + m]);
            *reinterpret_cast<float4*>(&As[kk][m]) = v;
        }
        // ---- load B tile into Bs[k][n] ----
        if (!TB) {
            int kk = tid >> 5;
            int n  = (tid & 31) * 4;
            float4 v = make_float4(0.f, 0.f, 0.f, 0.f);
            if (bn + n < N)
                v = *reinterpret_cast<const float4*>(&B[(long long)(k0 + kk) * N + bn + n]);
            *reinterpret_cast<float4*>(&Bs[kk][n]) = v;
        } else {
            int n  = tid >> 1;
            int kk = (tid & 1) * 4;
            float4 v = make_float4(0.f, 0.f, 0.f, 0.f);
            if (bn + n < N)
                v = *reinterpret_cast<const float4*>(&B[(long long)(bn + n) * K + k0 + kk]);
            Bs[kk + 0][n] = v.x; Bs[kk + 1][n] = v.y;
            Bs[kk + 2][n] = v.z; Bs[kk + 3][n] = v.w;
        }
        __syncthreads();

        #pragma unroll
        for (int k = 0; k < BK; k++) {
            float a[8], b[8];
            *reinterpret_cast<float4*>(&a[0]) = *reinterpret_cast<float4*>(&As[k][ty * 8]);
            *reinterpret_cast<float4*>(&a[4]) = *reinterpret_cast<float4*>(&As[k][ty * 8 + 4]);
            *reinterpret_cast<float4*>(&b[0]) = *reinterpret_cast<float4*>(&Bs[k][tx * 8]);
            *reinterpret_cast<float4*>(&b[4]) = *reinterpret_cast<float4*>(&Bs[k][tx * 8 + 4]);
            #pragma unroll
            for (int i = 0; i < 8; i++)
                #pragma unroll
                for (int j = 0; j < 8; j++)
                    acc[i][j] = fmaf(a[i], b[j], acc[i][j]);
        }
        __syncthreads();
    }

    // ---- epilogue ----
    #pragma unroll
    for (int i = 0; i < 8; i++) {
        int row = bm + ty * 8 + i;
        if (row >= M) continue;
        if (EPI) {
            float sc = scale[row], bi = bias[row];
            #pragma unroll
            for (int jj = 0; jj < 8; jj += 4) {
                int col = bn + tx * 8 + jj;
                if (col < N) {
                    long long base = (long long)row * N + col;
                    float4 r = *reinterpret_cast<const float4*>(
                        &resid[(long long)bz * sR + base]);
                    float4 o;
                    o.x = r.x + fmaf(acc[i][jj + 0], sc, bi);
                    o.y = r.y + fmaf(acc[i][jj + 1], sc, bi);
                    o.z = r.z + fmaf(acc[i][jj + 2], sc, bi);
                    o.w = r.w + fmaf(acc[i][jj + 3], sc, bi);
                    *reinterpret_cast<float4*>(&C[base]) = o;
                }
            }
        } else {
            #pragma unroll
            for (int jj = 0; jj < 8; jj += 4) {
                int col = bn + tx * 8 + jj;
                if (col < N) {
                    float4 o;
                    o.x = alpha * acc[i][jj + 0];
                    o.y = alpha * acc[i][jj + 1];
                    o.z = alpha * acc[i][jj + 2];
                    o.w = alpha * acc[i][jj + 3];
                    *reinterpret_cast<float4*>(&C[(long long)row * N + col]) = o;
                }
            }
        }
    }
}

// ---------------------------------------------------------------------------
// Launch
// ---------------------------------------------------------------------------
static inline dim3 gemm_grid(int M, int N, int batch) {
    return dim3((N + BN - 1) / BN, (M + BM - 1) / BM, batch);
}

extern "C" void kernel_launch(void* const* d_in, const int* in_sizes, int n_in,
                              void* d_out, int out_size) {
    const float* x       = (const float*)d_in[0];
    const float* w_theta = (const float*)d_in[1];
    const float* w_phi   = (const float*)d_in[2];
    const float* w_g     = (const float*)d_in[3];
    const float* w_out   = (const float*)d_in[4];
    const float* nscale  = (const float*)d_in[5];
    const float* nbias   = (const float*)d_in[6];
    float* out = (float*)d_out;

    float *xp, *theta, *phi, *gg, *attn, *o;
    cudaGetSymbolAddress((void**)&xp,    g_xp);
    cudaGetSymbolAddress((void**)&theta, g_theta);
    cudaGetSymbolAddress((void**)&phi,   g_phi);
    cudaGetSymbolAddress((void**)&gg,    g_gg);
    cudaGetSymbolAddress((void**)&attn,  g_attn);
    cudaGetSymbolAddress((void**)&o,     g_o);

    // 1) max pool on phi/g path
    {
        int total = NB * CC * PP;
        pool_kernel<<<(total + 255) / 256, 256>>>(x, xp, total);
    }

    // 2) theta = w_theta @ x     [512 x 3136 x 1024] per batch, NN
    gemm_kernel<false, false, false><<<gemm_grid(DD, THW, NB), 256>>>(
        w_theta, x, theta, DD, THW, CC,
        0LL, (long long)CC * THW, (long long)DD * THW, 1.0f,
        nullptr, nullptr, nullptr, 0LL);

    // 3) phi = w_phi @ xp, g = w_g @ xp   [512 x 784 x 1024] per batch, NN
    gemm_kernel<false, false, false><<<gemm_grid(DD, PP, NB), 256>>>(
        w_phi, xp, phi, DD, PP, CC,
        0LL, (long long)CC * PP, (long long)DD * PP, 1.0f,
        nullptr, nullptr, nullptr, 0LL);
    gemm_kernel<false, false, false><<<gemm_grid(DD, PP, NB), 256>>>(
        w_g, xp, gg, DD, PP, CC,
        0LL, (long long)CC * PP, (long long)DD * PP, 1.0f,
        nullptr, nullptr, nullptr, 0LL);

    // 4) logits = theta^T @ phi * D^-0.5   [3136 x 784 x 512] per batch, TN
    const float inv_sqrt_d = 0.044194173824159216f;  // 512^-0.5
    gemm_kernel<true, false, false><<<gemm_grid(THW, PP, NB), 256>>>(
        theta, phi, attn, THW, PP, DD,
        (long long)DD * THW, (long long)DD * PP, (long long)THW * PP, inv_sqrt_d,
        nullptr, nullptr, nullptr, 0LL);

    // 5) softmax over last dim (784), in place
    {
        int rows = NB * THW;                 // 25088 rows
        int warps_per_block = 8;             // 256 threads
        softmax_kernel<<<(rows + warps_per_block - 1) / warps_per_block, 256>>>(
            attn, rows, PP);
    }

    // 6) o = g @ attn^T    [512 x 3136 x 784] per batch, NT
    gemm_kernel<false, true, false><<<gemm_grid(DD, THW, NB), 256>>>(
        gg, attn, o, DD, THW, PP,
        (long long)DD * PP, (long long)THW * PP, (long long)DD * THW, 1.0f,
        nullptr, nullptr, nullptr, 0LL);

    // 7) out = x + (w_out @ o) * scale + bias   [1024 x 3136 x 512], NN + epilogue
    gemm_kernel<false, false, true><<<gemm_grid(CC, THW, NB), 256>>>(
        w_out, o, out, CC, THW, DD,
        0LL, (long long)DD * THW, (long long)CC * THW, 1.0f,
        nscale, nbias, x, (long long)CC * THW);
}

// round 3
// speedup vs baseline: 1.5358x; 1.5358x over previous
#include <cuda_runtime.h>
#include <cstdint>
#include <math.h>

// ---------------------------------------------------------------------------
// Problem dims
// ---------------------------------------------------------------------------
#define NB   8
#define CC   1024
#define TT   16
#define HH   14
#define WW   14
#define DD   512
#define THW  (TT*HH*WW)   // 3136
#define PH   (HH/2)
#define PW   (WW/2)
#define PP   (TT*PH*PW)   // 784

// Scratch
__device__ float g_xp   [NB*CC*PP];
__device__ float g_theta[NB*DD*THW];
__device__ float g_phi  [NB*DD*PP];
__device__ float g_gg   [NB*DD*PP];
__device__ float g_attn [NB*THW*PP];
__device__ float g_o    [NB*DD*THW];

// ---------------------------------------------------------------------------
// Tile geometry
// ---------------------------------------------------------------------------
#define BM  128
#define BN  128
#define BK  32
#define PAD 4
#define LDT (BK + PAD)          // 36 floats per staged row
#define TILE_FLOATS ((BM + BN) * LDT)
#define SMEM_BYTES  (2 * TILE_FLOATS * 4)   // double buffered: 73728 B

// ---------------------------------------------------------------------------
// PTX helpers (all target-independent: sm_80+ features only)
// ---------------------------------------------------------------------------
__device__ __forceinline__ uint32_t smem_u32(const void* p) {
    uint32_t a;
    asm("{ .reg .u64 t; cvta.to.shared.u64 t, %1; cvt.u32.u64 %0, t; }" : "=r"(a) : "l"(p));
    return a;
}
__device__ __forceinline__ uint32_t tf32r(float f) {
    uint32_t u;
    asm("cvt.rna.tf32.f32 %0, %1;" : "=r"(u) : "f"(f));
    return u;
}
__device__ __forceinline__ void cp16(uint32_t dst, const void* src, bool pred) {
    int sz = pred ? 16 : 0;
    asm volatile("cp.async.ca.shared.global [%0], [%1], 16, %2;"
                 :: "r"(dst), "l"(src), "r"(sz));
}
#define CP_COMMIT() asm volatile("cp.async.commit_group;" ::: "memory")
template<int N> __device__ __forceinline__ void cp_wait() {
    asm volatile("cp.async.wait_group %0;" :: "n"(N) : "memory");
}
__device__ __forceinline__ void mma8(float* c, const uint32_t* a, const uint32_t* b) {
    asm volatile(
        "mma.sync.aligned.m16n8k8.row.col.f32.tf32.tf32.f32 "
        "{%0,%1,%2,%3}, {%4,%5,%6,%7}, {%8,%9}, {%0,%1,%2,%3};"
        : "+f"(c[0]), "+f"(c[1]), "+f"(c[2]), "+f"(c[3])
        : "r"(a[0]), "r"(a[1]), "r"(a[2]), "r"(a[3]), "r"(b[0]), "r"(b[1]));
}

// ---------------------------------------------------------------------------
// Staging: gmem -> smem tile [rows][LDT], k-minor, tf32 conversion at use time
// ---------------------------------------------------------------------------
// K-contiguous: elem(r,k) = src[r*ld + k]   (cp.async, zfill OOB)
__device__ __forceinline__ void stage_kc(const float* __restrict__ src, uint32_t tile_u,
                                         int rows, int k0, int K, long long ld, int tid) {
    #pragma unroll
    for (int i = 0; i < 4; i++) {
        int idx = tid + i * 256;
        int r   = idx >> 3;
        int c4  = (idx & 7) * 4;
        bool ok = (r < rows) && (k0 + c4 < K);
        const float* s = ok ? (src + (long long)r * ld + k0 + c4) : src;
        cp16(tile_u + (uint32_t)(r * LDT + c4) * 4u, s, ok);
    }
}
// MN-contiguous: elem(r,k) = src[k*ld + r]   (scalar transpose, zero OOB)
__device__ __forceinline__ void stage_mn(const float* __restrict__ src, float* tile,
                                         int rows, int k0, int K, long long ld, int tid) {
    #pragma unroll
    for (int i = 0; i < 4; i++) {
        int idx = tid + i * 256;
        int kk  = idx >> 5;
        int r4  = (idx & 31) * 4;
        float4 v = make_float4(0.f, 0.f, 0.f, 0.f);
        if (k0 + kk < K && r4 < rows)
            v = *reinterpret_cast<const float4*>(src + (long long)(k0 + kk) * ld + r4);
        tile[(r4 + 0) * LDT + kk] = v.x;
        tile[(r4 + 1) * LDT + kk] = v.y;
        tile[(r4 + 2) * LDT + kk] = v.z;
        tile[(r4 + 3) * LDT + kk] = v.w;
    }
}

// ---------------------------------------------------------------------------
// tf32 mma.sync GEMM: C[M,N] = alpha * A·B^T  (A: MxK, B: NxK logical)
//   A_KC: A(m,k)=A[m*ldA+k] else A[k*ldA+m];  same for B with n.
//   EPI : C = resid + acc*scale[m] + bias[m]
// 128x128 CTA tile, BK=32, 8 warps (64x32 warp tiles), double-buffered.
// ---------------------------------------------------------------------------
template<bool A_KC, bool B_KC, bool EPI>
__global__ __launch_bounds__(256, 2)
void mma_gemm(const float* __restrict__ A, const float* __restrict__ B,
              float* __restrict__ C, int M, int N, int K,
              long long ldA, long long ldB, long long ldC,
              long long sA, long long sB, long long sC, float alpha,
              const float* __restrict__ scale, const float* __restrict__ bias,
              const float* __restrict__ resid, long long sR) {
    extern __shared__ float smem[];
    const int tid  = threadIdx.x;
    const int wid  = tid >> 5;
    const int lane = tid & 31;
    const int bz = blockIdx.z;
    const int bm = blockIdx.y * BM;
    const int bn = blockIdx.x * BN;

    A += (long long)bz * sA;
    B += (long long)bz * sB;
    C += (long long)bz * sC;

    const int rowsA = min(BM, M - bm);
    const int rowsB = min(BN, N - bn);
    const float* srcA = A_KC ? (A + (long long)bm * ldA) : (A + bm);
    const float* srcB = B_KC ? (B + (long long)bn * ldB) : (B + bn);

    float* tA[2] = { smem,               smem + TILE_FLOATS };
    float* tB[2] = { smem + BM * LDT,    smem + TILE_FLOATS + BM * LDT };
    const uint32_t smb = smem_u32(smem);
    const uint32_t uA[2] = { smb, smb + TILE_FLOATS * 4 };
    const uint32_t uB[2] = { smb + BM * LDT * 4, smb + (TILE_FLOATS + BM * LDT) * 4 };

    const int wm = (wid >> 2) * 64;   // warp M offset in tile
    const int wn = (wid & 3) * 32;    // warp N offset in tile

    float acc[4][4][4];
    #pragma unroll
    for (int i = 0; i < 4; i++)
        #pragma unroll
        for (int j = 0; j < 4; j++)
            #pragma unroll
            for (int e = 0; e < 4; e++) acc[i][j][e] = 0.f;

    const int KT = (K + BK - 1) / BK;

    // prologue: stage tile 0
    if (A_KC) stage_kc(srcA, uA[0], rowsA, 0, K, ldA, tid);
    else      stage_mn(srcA, tA[0], rowsA, 0, K, ldA, tid);
    if (B_KC) stage_kc(srcB, uB[0], rowsB, 0, K, ldB, tid);
    else      stage_mn(srcB, tB[0], rowsB, 0, K, ldB, tid);
    CP_COMMIT();

    for (int kt = 0; kt < KT; kt++) {
        const int buf = kt & 1;
        if (kt + 1 < KT) {
            const int nb = buf ^ 1;
            const int k0 = (kt + 1) * BK;
            if (A_KC) stage_kc(srcA, uA[nb], rowsA, k0, K, ldA, tid);
            else      stage_mn(srcA, tA[nb], rowsA, k0, K, ldA, tid);
            if (B_KC) stage_kc(srcB, uB[nb], rowsB, k0, K, ldB, tid);
            else      stage_mn(srcB, tB[nb], rowsB, k0, K, ldB, tid);
            CP_COMMIT();
            cp_wait<1>();
        } else {
            cp_wait<0>();
        }
        __syncthreads();

        const float* At = tA[buf];
        const float* Bt = tB[buf];
        #pragma unroll
        for (int ks = 0; ks < 4; ks++) {
            const int krow = ks * 8 + (lane & 3);
            uint32_t afr[4][4], bfr[4][2];
            #pragma unroll
            for (int i = 0; i < 4; i++) {
                const float* ap = At + (wm + i * 16 + (lane >> 2)) * LDT + krow;
                afr[i][0] = tf32r(ap[0]);
                afr[i][1] = tf32r(ap[8 * LDT]);
                afr[i][2] = tf32r(ap[4]);
                afr[i][3] = tf32r(ap[8 * LDT + 4]);
            }
            #pragma unroll
            for (int j = 0; j < 4; j++) {
                const float* bp = Bt + (wn + j * 8 + (lane >> 2)) * LDT + krow;
                bfr[j][0] = tf32r(bp[0]);
                bfr[j][1] = tf32r(bp[4]);
            }
            #pragma unroll
            for (int i = 0; i < 4; i++)
                #pragma unroll
                for (int j = 0; j < 4; j++)
                    mma8(acc[i][j], afr[i], bfr[j]);
        }
        __syncthreads();
    }

    // epilogue
    #pragma unroll
    for (int i = 0; i < 4; i++) {
        const int r0 = bm + wm + i * 16 + (lane >> 2);
        #pragma unroll
        for (int j = 0; j < 4; j++) {
            const int c = bn + wn + j * 8 + 2 * (lane & 3);
            if (c >= N) continue;
            #pragma unroll
            for (int h = 0; h < 2; h++) {
                const int r = r0 + h * 8;
                if (r >= M) continue;
                const long long base = (long long)r * ldC + c;
                float2 o;
                if (EPI) {
                    const float sc = scale[r], bi = bias[r];
                    const float2 rr = *reinterpret_cast<const float2*>(
                        &resid[(long long)bz * sR + base]);
                    o.x = rr.x + fmaf(acc[i][j][2 * h + 0], sc, bi);
                    o.y = rr.y + fmaf(acc[i][j][2 * h + 1], sc, bi);
                } else {
                    o.x = alpha * acc[i][j][2 * h + 0];
                    o.y = alpha * acc[i][j][2 * h + 1];
                }
                *reinterpret_cast<float2*>(&C[base]) = o;
            }
        }
    }
}

// ---------------------------------------------------------------------------
// Max pool (1,2,2)
// ---------------------------------------------------------------------------
__global__ void pool_kernel(const float* __restrict__ x, float* __restrict__ xp,
                            int total) {
    int idx = blockIdx.x * blockDim.x + threadIdx.x;
    if (idx >= total) return;
    int j   = idx % PW;
    int tmp = idx / PW;
    int i   = tmp % PH;
    tmp /= PH;
    const float* base = x + (long long)tmp * (HH*WW) + (2*i)*WW + 2*j;
    xp[idx] = fmaxf(fmaxf(base[0], base[1]), fmaxf(base[WW], base[WW+1]));
}

// ---------------------------------------------------------------------------
// Warp-per-row softmax (cols = 784)
// ---------------------------------------------------------------------------
__global__ void softmax_kernel(float* __restrict__ data, int rows, int cols) {
    int warp = blockIdx.x * (blockDim.x >> 5) + (threadIdx.x >> 5);
    if (warp >= rows) return;
    int lane = threadIdx.x & 31;
    float* row = data + (long long)warp * cols;
    float vals[25];
    int cnt = 0;
    float mx = -INFINITY;
    for (int c = lane; c < cols; c += 32) {
        float v = row[c];
        vals[cnt++] = v;
        mx = fmaxf(mx, v);
    }
    #pragma unroll
    for (int o = 16; o; o >>= 1) mx = fmaxf(mx, __shfl_xor_sync(0xffffffffu, mx, o));
    float sum = 0.f;
    for (int i = 0; i < cnt; i++) { vals[i] = __expf(vals[i] - mx); sum += vals[i]; }
    #pragma unroll
    for (int o = 16; o; o >>= 1) sum += __shfl_xor_sync(0xffffffffu, sum, o);
    float inv = 1.0f / sum;
    cnt = 0;
    for (int c = lane; c < cols; c += 32) row[c] = vals[cnt++] * inv;
}

// ---------------------------------------------------------------------------
// Launch
// ---------------------------------------------------------------------------
static inline dim3 g128(int M, int N, int b) {
    return dim3((N + BN - 1) / BN, (M + BM - 1) / BM, b);
}

extern "C" void kernel_launch(void* const* d_in, const int* in_sizes, int n_in,
                              void* d_out, int out_size) {
    const float* x       = (const float*)d_in[0];
    const float* w_theta = (const float*)d_in[1];
    const float* w_phi   = (const float*)d_in[2];
    const float* w_g     = (const float*)d_in[3];
    const float* w_out   = (const float*)d_in[4];
    const float* nscale  = (const float*)d_in[5];
    const float* nbias   = (const float*)d_in[6];
    float* out = (float*)d_out;

    float *xp, *theta, *phi, *gg, *attn, *o;
    cudaGetSymbolAddress((void**)&xp,    g_xp);
    cudaGetSymbolAddress((void**)&theta, g_theta);
    cudaGetSymbolAddress((void**)&phi,   g_phi);
    cudaGetSymbolAddress((void**)&gg,    g_gg);
    cudaGetSymbolAddress((void**)&attn,  g_attn);
    cudaGetSymbolAddress((void**)&o,     g_o);

    cudaFuncSetAttribute(mma_gemm<true,  false, false>, cudaFuncAttributeMaxDynamicSharedMemorySize, SMEM_BYTES);
    cudaFuncSetAttribute(mma_gemm<false, false, false>, cudaFuncAttributeMaxDynamicSharedMemorySize, SMEM_BYTES);
    cudaFuncSetAttribute(mma_gemm<true,  true,  false>, cudaFuncAttributeMaxDynamicSharedMemorySize, SMEM_BYTES);
    cudaFuncSetAttribute(mma_gemm<true,  false, true >, cudaFuncAttributeMaxDynamicSharedMemorySize, SMEM_BYTES);

    // 1) pool
    {
        int total = NB * CC * PP;
        pool_kernel<<<(total + 255) / 256, 256>>>(x, xp, total);
    }

    // 2) theta = w_theta @ x : M=512 N=3136 K=1024; A KC, B MN
    mma_gemm<true, false, false><<<g128(DD, THW, NB), 256, SMEM_BYTES>>>(
        w_theta, x, theta, DD, THW, CC,
        CC, THW, THW, 0LL, (long long)CC * THW, (long long)DD * THW,
        1.0f, nullptr, nullptr, nullptr, 0LL);

    // 3) phi / g = w @ xp : M=512 N=784 K=1024; A KC, B MN
    mma_gemm<true, false, false><<<g128(DD, PP, NB), 256, SMEM_BYTES>>>(
        w_phi, xp, phi, DD, PP, CC,
        CC, PP, PP, 0LL, (long long)CC * PP, (long long)DD * PP,
        1.0f, nullptr, nullptr, nullptr, 0LL);
    mma_gemm<true, false, false><<<g128(DD, PP, NB), 256, SMEM_BYTES>>>(
        w_g, xp, gg, DD, PP, CC,
        CC, PP, PP, 0LL, (long long)CC * PP, (long long)DD * PP,
        1.0f, nullptr, nullptr, nullptr, 0LL);

    // 4) logits = theta^T @ phi * D^-0.5 : M=3136 N=784 K=512; A MN, B MN
    mma_gemm<false, false, false><<<g128(THW, PP, NB), 256, SMEM_BYTES>>>(
        theta, phi, attn, THW, PP, DD,
        THW, PP, PP, (long long)DD * THW, (long long)DD * PP, (long long)THW * PP,
        0.044194173824159216f, nullptr, nullptr, nullptr, 0LL);

    // 5) softmax rows over 784
    softmax_kernel<<<(NB * THW + 7) / 8, 256>>>(attn, NB * THW, PP);

    // 6) o = g @ attn^T : M=512 N=3136 K=784; A KC, B KC
    mma_gemm<true, true, false><<<g128(DD, THW, NB), 256, SMEM_BYTES>>>(
        gg, attn, o, DD, THW, PP,
        PP, PP, THW, (long long)DD * PP, (long long)THW * PP, (long long)DD * THW,
        1.0f, nullptr, nullptr, nullptr, 0LL);

    // 7) out = x + (w_out @ o)*scale + bias : M=1024 N=3136 K=512; A KC, B MN, EPI
    mma_gemm<true, false, true><<<g128(CC, THW, NB), 256, SMEM_BYTES>>>(
        w_out, o, out, CC, THW, DD,
        DD, THW, THW, 0LL, (long long)DD * THW, (long long)CC * THW,
        1.0f, nscale, nbias, x, (long long)CC * THW);
}

// round 5
// speedup vs baseline: 1.9936x; 1.2981x over previous
#include <cuda_runtime.h>
#include <cstdint>
#include <math.h>

// ---------------------------------------------------------------------------
// Problem dims
// ---------------------------------------------------------------------------
#define NB   8
#define CC   1024
#define TT   16
#define HH   14
#define WW   14
#define DD   512
#define THW  (TT*HH*WW)   // 3136
#define PH   (HH/2)
#define PW   (WW/2)
#define PP   (TT*PH*PW)   // 784

// Scratch
__device__ float g_xp   [NB*CC*PP];
__device__ float g_theta[NB*DD*THW];
__device__ float g_phi  [NB*DD*PP];
__device__ float g_gg   [NB*DD*PP];
__device__ float g_attn [NB*THW*PP];
__device__ float g_o    [NB*DD*THW];

// ---------------------------------------------------------------------------
// Tile geometry: 128x128 CTA tile, BK=32, 128 threads (4 warps, 64x64 each)
// ---------------------------------------------------------------------------
#define BM  128
#define BN  128
#define BK  32
#define NT  128
#define PAD 4
#define LDT (BK + PAD)          // 36
#define TILE_FLOATS ((BM + BN) * LDT)
#define SMEM_BYTES  (2 * TILE_FLOATS * 4)   // 73728 B

// ---------------------------------------------------------------------------
// PTX helpers (sm_80-level, target-independent)
// ---------------------------------------------------------------------------
__device__ __forceinline__ uint32_t smem_u32(const void* p) {
    uint32_t a;
    asm("{ .reg .u64 t; cvta.to.shared.u64 t, %1; cvt.u32.u64 %0, t; }" : "=r"(a) : "l"(p));
    return a;
}
__device__ __forceinline__ uint32_t tf32r(float f) {
    uint32_t u;
    asm("cvt.rna.tf32.f32 %0, %1;" : "=r"(u) : "f"(f));
    return u;
}
__device__ __forceinline__ void cp16(uint32_t dst, const void* src, bool pred) {
    int sz = pred ? 16 : 0;
    asm volatile("cp.async.ca.shared.global [%0], [%1], 16, %2;"
                 :: "r"(dst), "l"(src), "r"(sz));
}
#define CP_COMMIT() asm volatile("cp.async.commit_group;" ::: "memory")
template<int N> __device__ __forceinline__ void cp_wait() {
    asm volatile("cp.async.wait_group %0;" :: "n"(N) : "memory");
}
__device__ __forceinline__ void mma8(float* c, const uint32_t* a, const uint32_t* b) {
    asm volatile(
        "mma.sync.aligned.m16n8k8.row.col.f32.tf32.tf32.f32 "
        "{%0,%1,%2,%3}, {%4,%5,%6,%7}, {%8,%9}, {%0,%1,%2,%3};"
        : "+f"(c[0]), "+f"(c[1]), "+f"(c[2]), "+f"(c[3])
        : "r"(a[0]), "r"(a[1]), "r"(a[2]), "r"(a[3]), "r"(b[0]), "r"(b[1]));
}

// ---------------------------------------------------------------------------
// Staging
// ---------------------------------------------------------------------------
// K-contiguous: elem(r,k)=src[r*ld+k]  (cp.async, zfill OOB). 8 iters x 16B.
__device__ __forceinline__ void stage_kc(const float* __restrict__ src, uint32_t tile_u,
                                         int rows, int k0, int K, long long ld, int tid) {
    #pragma unroll
    for (int i = 0; i < 8; i++) {
        int idx = tid + i * NT;
        int r   = idx >> 3;
        int c4  = (idx & 7) * 4;
        bool ok = (r < rows) && (k0 + c4 < K);
        const float* s = ok ? (src + (long long)r * ld + k0 + c4) : src;
        cp16(tile_u + (uint32_t)(r * LDT + c4) * 4u, s, ok);
    }
}
// MN-contiguous: elem(r,k)=src[k*ld+r]. Split into load (regs) / store phases.
// Lanes span k -> conflict-free scalar STS (addr = (r4+j)*36 + kk, kk distinct mod 32).
__device__ __forceinline__ void stage_mn_load(const float* __restrict__ src, float4* v,
                                              int rows, int k0, int K, long long ld, int tid) {
    #pragma unroll
    for (int i = 0; i < 8; i++) {
        int idx = tid + i * NT;
        int kk  = idx & 31;
        int r4  = (idx >> 5) * 4;
        float4 t = make_float4(0.f, 0.f, 0.f, 0.f);
        if (k0 + kk < K && r4 < rows)
            t = *reinterpret_cast<const float4*>(src + (long long)(k0 + kk) * ld + r4);
        v[i] = t;
    }
}
__device__ __forceinline__ void stage_mn_store(float* tile, const float4* v, int tid) {
    #pragma unroll
    for (int i = 0; i < 8; i++) {
        int idx = tid + i * NT;
        int kk  = idx & 31;
        int r4  = (idx >> 5) * 4;
        tile[(r4 + 0) * LDT + kk] = v[i].x;
        tile[(r4 + 1) * LDT + kk] = v[i].y;
        tile[(r4 + 2) * LDT + kk] = v[i].z;
        tile[(r4 + 3) * LDT + kk] = v[i].w;
    }
}

// ---------------------------------------------------------------------------
// tf32 mma.sync GEMM: C[M,N] = alpha * A·B^T  (A: MxK, B: NxK logical)
// 4 warps, 64x64 warp tile, double-buffered smem.
// ---------------------------------------------------------------------------
template<bool A_KC, bool B_KC, bool EPI>
__global__ __launch_bounds__(NT, 2)
void mma_gemm(const float* __restrict__ A, const float* __restrict__ B,
              float* __restrict__ C, int M, int N, int K,
              long long ldA, long long ldB, long long ldC,
              long long sA, long long sB, long long sC, float alpha,
              const float* __restrict__ scale, const float* __restrict__ bias,
              const float* __restrict__ resid, long long sR) {
    extern __shared__ float smem[];
    const int tid  = threadIdx.x;
    const int wid  = tid >> 5;
    const int lane = tid & 31;
    const int bz = blockIdx.z;
    const int bm = blockIdx.y * BM;
    const int bn = blockIdx.x * BN;

    A += (long long)bz * sA;
    B += (long long)bz * sB;
    C += (long long)bz * sC;

    const int rowsA = min(BM, M - bm);
    const int rowsB = min(BN, N - bn);
    const float* srcA = A_KC ? (A + (long long)bm * ldA) : (A + bm);
    const float* srcB = B_KC ? (B + (long long)bn * ldB) : (B + bn);

    float* tA[2] = { smem,            smem + TILE_FLOATS };
    float* tB[2] = { smem + BM * LDT, smem + TILE_FLOATS + BM * LDT };
    const uint32_t smb = smem_u32(smem);
    const uint32_t uA[2] = { smb, smb + TILE_FLOATS * 4 };
    const uint32_t uB[2] = { smb + BM * LDT * 4, smb + (TILE_FLOATS + BM * LDT) * 4 };

    const int wm = (wid >> 1) * 64;
    const int wn = (wid & 1) * 64;

    float acc[4][8][4];
    #pragma unroll
    for (int i = 0; i < 4; i++)
        #pragma unroll
        for (int j = 0; j < 8; j++)
            #pragma unroll
            for (int e = 0; e < 4; e++) acc[i][j][e] = 0.f;

    const int KT = (K + BK - 1) / BK;

    // prologue: stage tile 0 into buffer 0
    {
        float4 va[8], vb[8];
        if (A_KC) stage_kc(srcA, uA[0], rowsA, 0, K, ldA, tid);
        else      stage_mn_load(srcA, va, rowsA, 0, K, ldA, tid);
        if (B_KC) stage_kc(srcB, uB[0], rowsB, 0, K, ldB, tid);
        else      stage_mn_load(srcB, vb, rowsB, 0, K, ldB, tid);
        CP_COMMIT();
        if (!A_KC) stage_mn_store(tA[0], va, tid);
        if (!B_KC) stage_mn_store(tB[0], vb, tid);
        cp_wait<0>();
        __syncthreads();
    }

    for (int kt = 0; kt < KT; kt++) {
        const int buf = kt & 1;
        const int nb  = buf ^ 1;
        const bool pf = (kt + 1 < KT);
        float4 va[8], vb[8];

        // issue next-tile loads (cp.async / LDG) before the MMA section
        if (pf) {
            const int k0 = (kt + 1) * BK;
            if (A_KC) stage_kc(srcA, uA[nb], rowsA, k0, K, ldA, tid);
            else      stage_mn_load(srcA, va, rowsA, k0, K, ldA, tid);
            if (B_KC) stage_kc(srcB, uB[nb], rowsB, k0, K, ldB, tid);
            else      stage_mn_load(srcB, vb, rowsB, k0, K, ldB, tid);
            CP_COMMIT();
        }

        // MMA on current buffer
        const float* At = tA[buf];
        const float* Bt = tB[buf];
        #pragma unroll
        for (int ks = 0; ks < 4; ks++) {
            const int krow = ks * 8 + (lane & 3);
            uint32_t afr[4][4], bfr[8][2];
            #pragma unroll
            for (int i = 0; i < 4; i++) {
                const float* ap = At + (wm + i * 16 + (lane >> 2)) * LDT + krow;
                afr[i][0] = tf32r(ap[0]);
                afr[i][1] = tf32r(ap[8 * LDT]);
                afr[i][2] = tf32r(ap[4]);
                afr[i][3] = tf32r(ap[8 * LDT + 4]);
            }
            #pragma unroll
            for (int j = 0; j < 8; j++) {
                const float* bp = Bt + (wn + j * 8 + (lane >> 2)) * LDT + krow;
                bfr[j][0] = tf32r(bp[0]);
                bfr[j][1] = tf32r(bp[4]);
            }
            #pragma unroll
            for (int i = 0; i < 4; i++)
                #pragma unroll
                for (int j = 0; j < 8; j++)
                    mma8(acc[i][j], afr[i], bfr[j]);
        }

        // complete next-tile staging
        if (pf) {
            if (!A_KC) stage_mn_store(tA[nb], va, tid);
            if (!B_KC) stage_mn_store(tB[nb], vb, tid);
            cp_wait<0>();
        }
        __syncthreads();
    }

    // epilogue
    #pragma unroll
    for (int i = 0; i < 4; i++) {
        const int r0 = bm + wm + i * 16 + (lane >> 2);
        #pragma unroll
        for (int j = 0; j < 8; j++) {
            const int c = bn + wn + j * 8 + 2 * (lane & 3);
            if (c >= N) continue;
            #pragma unroll
            for (int h = 0; h < 2; h++) {
                const int r = r0 + h * 8;
                if (r >= M) continue;
                const long long base = (long long)r * ldC + c;
                float2 o;
                if (EPI) {
                    const float sc = scale[r], bi = bias[r];
                    const float2 rr = *reinterpret_cast<const float2*>(
                        &resid[(long long)bz * sR + base]);
                    o.x = rr.x + fmaf(acc[i][j][2 * h + 0], sc, bi);
                    o.y = rr.y + fmaf(acc[i][j][2 * h + 1], sc, bi);
                } else {
                    o.x = alpha * acc[i][j][2 * h + 0];
                    o.y = alpha * acc[i][j][2 * h + 1];
                }
                *reinterpret_cast<float2*>(&C[base]) = o;
            }
        }
    }
}

// ---------------------------------------------------------------------------
// Max pool (1,2,2)
// ---------------------------------------------------------------------------
__global__ void pool_kernel(const float* __restrict__ x, float* __restrict__ xp,
                            int total) {
    int idx = blockIdx.x * blockDim.x + threadIdx.x;
    if (idx >= total) return;
    int j   = idx % PW;
    int tmp = idx / PW;
    int i   = tmp % PH;
    tmp /= PH;
    const float* base = x + (long long)tmp * (HH*WW) + (2*i)*WW + 2*j;
    xp[idx] = fmaxf(fmaxf(base[0], base[1]), fmaxf(base[WW], base[WW+1]));
}

// ---------------------------------------------------------------------------
// Warp-per-row softmax (cols = 784)
// ---------------------------------------------------------------------------
__global__ void softmax_kernel(float* __restrict__ data, int rows, int cols) {
    int warp = blockIdx.x * (blockDim.x >> 5) + (threadIdx.x >> 5);
    if (warp >= rows) return;
    int lane = threadIdx.x & 31;
    float* row = data + (long long)warp * cols;
    float vals[25];
    int cnt = 0;
    float mx = -INFINITY;
    for (int c = lane; c < cols; c += 32) {
        float v = row[c];
        vals[cnt++] = v;
        mx = fmaxf(mx, v);
    }
    #pragma unroll
    for (int o = 16; o; o >>= 1) mx = fmaxf(mx, __shfl_xor_sync(0xffffffffu, mx, o));
    float sum = 0.f;
    for (int i = 0; i < cnt; i++) { vals[i] = __expf(vals[i] - mx); sum += vals[i]; }
    #pragma unroll
    for (int o = 16; o; o >>= 1) sum += __shfl_xor_sync(0xffffffffu, sum, o);
    float inv = 1.0f / sum;
    cnt = 0;
    for (int c = lane; c < cols; c += 32) row[c] = vals[cnt++] * inv;
}

// ---------------------------------------------------------------------------
// Launch
// ---------------------------------------------------------------------------
static inline dim3 g128(int M, int N, int b) {
    return dim3((N + BN - 1) / BN, (M + BM - 1) / BM, b);
}

extern "C" void kernel_launch(void* const* d_in, const int* in_sizes, int n_in,
                              void* d_out, int out_size) {
    const float* x       = (const float*)d_in[0];
    const float* w_theta = (const float*)d_in[1];
    const float* w_phi   = (const float*)d_in[2];
    const float* w_g     = (const float*)d_in[3];
    const float* w_out   = (const float*)d_in[4];
    const float* nscale  = (const float*)d_in[5];
    const float* nbias   = (const float*)d_in[6];
    float* out = (float*)d_out;

    float *xp, *theta, *phi, *gg, *attn, *o;
    cudaGetSymbolAddress((void**)&xp,    g_xp);
    cudaGetSymbolAddress((void**)&theta, g_theta);
    cudaGetSymbolAddress((void**)&phi,   g_phi);
    cudaGetSymbolAddress((void**)&gg,    g_gg);
    cudaGetSymbolAddress((void**)&attn,  g_attn);
    cudaGetSymbolAddress((void**)&o,     g_o);

    cudaFuncSetAttribute(mma_gemm<true,  false, false>, cudaFuncAttributeMaxDynamicSharedMemorySize, SMEM_BYTES);
    cudaFuncSetAttribute(mma_gemm<false, false, false>, cudaFuncAttributeMaxDynamicSharedMemorySize, SMEM_BYTES);
    cudaFuncSetAttribute(mma_gemm<true,  true,  false>, cudaFuncAttributeMaxDynamicSharedMemorySize, SMEM_BYTES);
    cudaFuncSetAttribute(mma_gemm<true,  false, true >, cudaFuncAttributeMaxDynamicSharedMemorySize, SMEM_BYTES);

    // 1) pool
    {
        int total = NB * CC * PP;
        pool_kernel<<<(total + 255) / 256, 256>>>(x, xp, total);
    }

    // 2) theta = w_theta @ x : M=512 N=3136 K=1024; A KC, B MN
    mma_gemm<true, false, false><<<g128(DD, THW, NB), NT, SMEM_BYTES>>>(
        w_theta, x, theta, DD, THW, CC,
        CC, THW, THW, 0LL, (long long)CC * THW, (long long)DD * THW,
        1.0f, nullptr, nullptr, nullptr, 0LL);

    // 3) phi / g = w @ xp : M=512 N=784 K=1024; A KC, B MN
    mma_gemm<true, false, false><<<g128(DD, PP, NB), NT, SMEM_BYTES>>>(
        w_phi, xp, phi, DD, PP, CC,
        CC, PP, PP, 0LL, (long long)CC * PP, (long long)DD * PP,
        1.0f, nullptr, nullptr, nullptr, 0LL);
    mma_gemm<true, false, false><<<g128(DD, PP, NB), NT, SMEM_BYTES>>>(
        w_g, xp, gg, DD, PP, CC,
        CC, PP, PP, 0LL, (long long)CC * PP, (long long)DD * PP,
        1.0f, nullptr, nullptr, nullptr, 0LL);

    // 4) logits = theta^T @ phi * D^-0.5 : M=3136 N=784 K=512; A MN, B MN
    mma_gemm<false, false, false><<<g128(THW, PP, NB), NT, SMEM_BYTES>>>(
        theta, phi, attn, THW, PP, DD,
        THW, PP, PP, (long long)DD * THW, (long long)DD * PP, (long long)THW * PP,
        0.044194173824159216f, nullptr, nullptr, nullptr, 0LL);

    // 5) softmax rows over 784
    softmax_kernel<<<(NB * THW + 7) / 8, 256>>>(attn, NB * THW, PP);

    // 6) o = g @ attn^T : M=512 N=3136 K=784; A KC, B KC
    mma_gemm<true, true, false><<<g128(DD, THW, NB), NT, SMEM_BYTES>>>(
        gg, attn, o, DD, THW, PP,
        PP, PP, THW, (long long)DD * PP, (long long)THW * PP, (long long)DD * THW,
        1.0f, nullptr, nullptr, nullptr, 0LL);

    // 7) out = x + (w_out @ o)*scale + bias : M=1024 N=3136 K=512; A KC, B MN, EPI
    mma_gemm<true, false, true><<<g128(CC, THW, NB), NT, SMEM_BYTES>>>(
        w_out, o, out, CC, THW, DD,
        DD, THW, THW, 0LL, (long long)DD * THW, (long long)CC * THW,
        1.0f, nscale, nbias, x, (long long)CC * THW);
}

// round 7
// speedup vs baseline: 2.5745x; 1.2914x over previous
#include <cuda_runtime.h>
#include <cstdint>
#include <math.h>

// ---------------------------------------------------------------------------
// Problem dims
// ---------------------------------------------------------------------------
#define NB   8
#define CC   1024
#define TT   16
#define HH   14
#define WW   14
#define DD   512
#define THW  (TT*HH*WW)   // 3136
#define PH   (HH/2)
#define PW   (WW/2)
#define PP   (TT*PH*PW)   // 784

// Scratch (all K-contiguous layouts)
__device__ float g_xT    [NB*THW*CC];   // x^T      [N, THW, C]
__device__ float g_xpT   [NB*PP*CC];    // pooled^T [N, PP, C]
__device__ float g_thetaT[NB*THW*DD];   // theta^T  [N, THW, D]
__device__ float g_phiT  [NB*PP*DD];    // phi^T    [N, PP, D]
__device__ float g_g     [NB*DD*PP];    // g        [N, D, PP]
__device__ float g_attn  [NB*THW*PP];   // attn     [N, THW, PP]
__device__ float g_oT    [NB*THW*DD];   // o^T      [N, THW, D]

// ---------------------------------------------------------------------------
// Tile geometry: 128x128 CTA tile, BK=32, 128 threads (4 warps, 64x64 each)
// ---------------------------------------------------------------------------
#define BM  128
#define BN  128
#define BK  32
#define NT  128
#define PAD 4
#define LDT (BK + PAD)          // 36
#define TILE_FLOATS ((BM + BN) * LDT)
#define SMEM_BYTES  (2 * TILE_FLOATS * 4)   // 73728 B

// ---------------------------------------------------------------------------
// PTX helpers (sm_80-level, target-independent)
// ---------------------------------------------------------------------------
__device__ __forceinline__ uint32_t tf32r(float f) {
    uint32_t u;
    asm("cvt.rna.tf32.f32 %0, %1;" : "=r"(u) : "f"(f));
    return u;
}
__device__ __forceinline__ uint32_t smem_u32(const void* p) {
    uint32_t a;
    asm("{ .reg .u64 t; cvta.to.shared.u64 t, %1; cvt.u32.u64 %0, t; }" : "=r"(a) : "l"(p));
    return a;
}
__device__ __forceinline__ void cp16(uint32_t dst, const void* src, bool pred) {
    int sz = pred ? 16 : 0;
    asm volatile("cp.async.ca.shared.global [%0], [%1], 16, %2;"
                 :: "r"(dst), "l"(src), "r"(sz));
}
#define CP_COMMIT() asm volatile("cp.async.commit_group;" ::: "memory")
template<int N> __device__ __forceinline__ void cp_wait() {
    asm volatile("cp.async.wait_group %0;" :: "n"(N) : "memory");
}
__device__ __forceinline__ void mma8(float* c, const uint32_t* a, const uint32_t* b) {
    asm volatile(
        "mma.sync.aligned.m16n8k8.row.col.f32.tf32.tf32.f32 "
        "{%0,%1,%2,%3}, {%4,%5,%6,%7}, {%8,%9}, {%0,%1,%2,%3};"
        : "+f"(c[0]), "+f"(c[1]), "+f"(c[2]), "+f"(c[3])
        : "r"(a[0]), "r"(a[1]), "r"(a[2]), "r"(a[3]), "r"(b[0]), "r"(b[1]));
}

// K-contiguous staging: elem(r,k)=src[r*ld+k], cp.async 16B, zfill OOB.
__device__ __forceinline__ void stage_kc(const float* __restrict__ src, uint32_t tile_u,
                                         int rows, int k0, int K, long long ld, int tid) {
    #pragma unroll
    for (int i = 0; i < 8; i++) {
        int idx = tid + i * NT;
        int r   = idx >> 3;
        int c4  = (idx & 7) * 4;
        bool ok = (r < rows) && (k0 + c4 < K);
        const float* s = ok ? (src + (long long)r * ld + k0 + c4) : src;
        cp16(tile_u + (uint32_t)(r * LDT + c4) * 4u, s, ok);
    }
}

// ---------------------------------------------------------------------------
// tf32 mma.sync GEMM: C[M,N] = alpha * A·B^T, both operands K-contiguous.
// 4 warps, 64x64 warp tile, double-buffered cp.async smem.
// EPI: C = resid + acc*scale[m] + bias[m]
// ---------------------------------------------------------------------------
template<bool EPI>
__global__ __launch_bounds__(NT, 2)
void mma_gemm(const float* __restrict__ A, const float* __restrict__ B,
              float* __restrict__ C, int M, int N, int K,
              long long ldA, long long ldB, long long ldC,
              long long sA, long long sB, long long sC, float alpha,
              const float* __restrict__ scale, const float* __restrict__ bias,
              const float* __restrict__ resid, long long sR) {
    extern __shared__ float smem[];
    const int tid  = threadIdx.x;
    const int wid  = tid >> 5;
    const int lane = tid & 31;
    const int bz = blockIdx.z;
    const int bm = blockIdx.y * BM;
    const int bn = blockIdx.x * BN;

    A += (long long)bz * sA;
    B += (long long)bz * sB;
    C += (long long)bz * sC;

    const int rowsA = min(BM, M - bm);
    const int rowsB = min(BN, N - bn);
    const float* srcA = A + (long long)bm * ldA;
    const float* srcB = B + (long long)bn * ldB;

    float* tA[2] = { smem,            smem + TILE_FLOATS };
    float* tB[2] = { smem + BM * LDT, smem + TILE_FLOATS + BM * LDT };
    const uint32_t smb = smem_u32(smem);
    const uint32_t uA[2] = { smb, smb + TILE_FLOATS * 4 };
    const uint32_t uB[2] = { smb + BM * LDT * 4, smb + (TILE_FLOATS + BM * LDT) * 4 };

    const int wm = (wid >> 1) * 64;
    const int wn = (wid & 1) * 64;

    float acc[4][8][4];
    #pragma unroll
    for (int i = 0; i < 4; i++)
        #pragma unroll
        for (int j = 0; j < 8; j++)
            #pragma unroll
            for (int e = 0; e < 4; e++) acc[i][j][e] = 0.f;

    const int KT = (K + BK - 1) / BK;

    // prologue
    stage_kc(srcA, uA[0], rowsA, 0, K, ldA, tid);
    stage_kc(srcB, uB[0], rowsB, 0, K, ldB, tid);
    CP_COMMIT();
    cp_wait<0>();
    __syncthreads();

    for (int kt = 0; kt < KT; kt++) {
        const int buf = kt & 1;
        const bool pf = (kt + 1 < KT);
        if (pf) {
            const int k0 = (kt + 1) * BK;
            stage_kc(srcA, uA[buf ^ 1], rowsA, k0, K, ldA, tid);
            stage_kc(srcB, uB[buf ^ 1], rowsB, k0, K, ldB, tid);
            CP_COMMIT();
        }

        const float* At = tA[buf];
        const float* Bt = tB[buf];
        #pragma unroll
        for (int ks = 0; ks < 4; ks++) {
            const int krow = ks * 8 + (lane & 3);
            uint32_t afr[4][4], bfr[8][2];
            #pragma unroll
            for (int i = 0; i < 4; i++) {
                const float* ap = At + (wm + i * 16 + (lane >> 2)) * LDT + krow;
                afr[i][0] = tf32r(ap[0]);
                afr[i][1] = tf32r(ap[8 * LDT]);
                afr[i][2] = tf32r(ap[4]);
                afr[i][3] = tf32r(ap[8 * LDT + 4]);
            }
            #pragma unroll
            for (int j = 0; j < 8; j++) {
                const float* bp = Bt + (wn + j * 8 + (lane >> 2)) * LDT + krow;
                bfr[j][0] = tf32r(bp[0]);
                bfr[j][1] = tf32r(bp[4]);
            }
            #pragma unroll
            for (int i = 0; i < 4; i++)
                #pragma unroll
                for (int j = 0; j < 8; j++)
                    mma8(acc[i][j], afr[i], bfr[j]);
        }

        if (pf) cp_wait<0>();
        __syncthreads();
    }

    // epilogue
    #pragma unroll
    for (int i = 0; i < 4; i++) {
        const int r0 = bm + wm + i * 16 + (lane >> 2);
        #pragma unroll
        for (int j = 0; j < 8; j++) {
            const int c = bn + wn + j * 8 + 2 * (lane & 3);
            if (c >= N) continue;
            #pragma unroll
            for (int h = 0; h < 2; h++) {
                const int r = r0 + h * 8;
                if (r >= M) continue;
                const long long base = (long long)r * ldC + c;
                float2 o;
                if (EPI) {
                    const float sc = scale[r], bi = bias[r];
                    const float2 rr = *reinterpret_cast<const float2*>(
                        &resid[(long long)bz * sR + base]);
                    o.x = rr.x + fmaf(acc[i][j][2 * h + 0], sc, bi);
                    o.y = rr.y + fmaf(acc[i][j][2 * h + 1], sc, bi);
                } else {
                    o.x = alpha * acc[i][j][2 * h + 0];
                    o.y = alpha * acc[i][j][2 * h + 1];
                }
                *reinterpret_cast<float2*>(&C[base]) = o;
            }
        }
    }
}

// ---------------------------------------------------------------------------
// Tiled transpose: x [C, THW] -> xT [THW, C] per batch (3136 = 98*32, 1024 = 32*32)
// ---------------------------------------------------------------------------
__global__ void transpose_kernel(const float* __restrict__ x, float* __restrict__ xT) {
    __shared__ float tile[32][33];
    const int bz = blockIdx.z;
    const float* src = x  + (long long)bz * CC * THW;
    float*       dst = xT + (long long)bz * THW * CC;
    const int t0 = blockIdx.x * 32;
    const int c0 = blockIdx.y * 32;
    #pragma unroll
    for (int j = threadIdx.y; j < 32; j += 8)
        tile[j][threadIdx.x] = src[(long long)(c0 + j) * THW + t0 + threadIdx.x];
    __syncthreads();
    #pragma unroll
    for (int j = threadIdx.y; j < 32; j += 8)
        dst[(long long)(t0 + j) * CC + c0 + threadIdx.x] = tile[threadIdx.x][j];
}

// ---------------------------------------------------------------------------
// Pooled transpose: xT [THW, C] -> xpT [PP, C]; max over the 2x2 spatial window
// (4 consecutive-row reads of xT, fully coalesced).
// ---------------------------------------------------------------------------
__global__ void pooltrans_kernel(const float* __restrict__ xT, float* __restrict__ xpT) {
    const int p  = blockIdx.x;            // 0..PP-1
    const int nb = blockIdx.y;
    const int t  = p / (PH * PW);
    const int ij = p % (PH * PW);
    const int i  = ij / PW;
    const int j  = ij % PW;
    const int r00 = t * (HH * WW) + (2 * i) * WW + 2 * j;
    const float4* s0 = (const float4*)(xT + ((long long)nb * THW + r00) * CC);
    const float4* s1 = s0 + CC / 4;                                    // r00 + 1
    const float4* s2 = (const float4*)(xT + ((long long)nb * THW + r00 + WW) * CC);
    const float4* s3 = s2 + CC / 4;                                    // r00 + WW + 1
    float4* d = (float4*)(xpT + ((long long)nb * PP + p) * CC);
    const int c = threadIdx.x;            // 256 threads x float4 = 1024 floats
    float4 a = s0[c], b = s1[c], e = s2[c], f = s3[c];
    float4 o;
    o.x = fmaxf(fmaxf(a.x, b.x), fmaxf(e.x, f.x));
    o.y = fmaxf(fmaxf(a.y, b.y), fmaxf(e.y, f.y));
    o.z = fmaxf(fmaxf(a.z, b.z), fmaxf(e.z, f.z));
    o.w = fmaxf(fmaxf(a.w, b.w), fmaxf(e.w, f.w));
    d[c] = o;
}

// ---------------------------------------------------------------------------
// Warp-per-row softmax (cols = 784)
// ---------------------------------------------------------------------------
__global__ void softmax_kernel(float* __restrict__ data, int rows, int cols) {
    int warp = blockIdx.x * (blockDim.x >> 5) + (threadIdx.x >> 5);
    if (warp >= rows) return;
    int lane = threadIdx.x & 31;
    float* row = data + (long long)warp * cols;
    float vals[25];
    int cnt = 0;
    float mx = -INFINITY;
    for (int c = lane; c < cols; c += 32) {
        float v = row[c];
        vals[cnt++] = v;
        mx = fmaxf(mx, v);
    }
    #pragma unroll
    for (int o = 16; o; o >>= 1) mx = fmaxf(mx, __shfl_xor_sync(0xffffffffu, mx, o));
    float sum = 0.f;
    for (int i = 0; i < cnt; i++) { vals[i] = __expf(vals[i] - mx); sum += vals[i]; }
    #pragma unroll
    for (int o = 16; o; o >>= 1) sum += __shfl_xor_sync(0xffffffffu, sum, o);
    float inv = 1.0f / sum;
    cnt = 0;
    for (int c = lane; c < cols; c += 32) row[c] = vals[cnt++] * inv;
}

// ---------------------------------------------------------------------------
// Launch
// ---------------------------------------------------------------------------
static inline dim3 g128(int M, int N, int b) {
    return dim3((N + BN - 1) / BN, (M + BM - 1) / BM, b);
}

extern "C" void kernel_launch(void* const* d_in, const int* in_sizes, int n_in,
                              void* d_out, int out_size) {
    const float* x       = (const float*)d_in[0];
    const float* w_theta = (const float*)d_in[1];
    const float* w_phi   = (const float*)d_in[2];
    const float* w_g     = (const float*)d_in[3];
    const float* w_out   = (const float*)d_in[4];
    const float* nscale  = (const float*)d_in[5];
    const float* nbias   = (const float*)d_in[6];
    float* out = (float*)d_out;

    float *xT, *xpT, *thetaT, *phiT, *gg, *attn, *oT;
    cudaGetSymbolAddress((void**)&xT,     g_xT);
    cudaGetSymbolAddress((void**)&xpT,    g_xpT);
    cudaGetSymbolAddress((void**)&thetaT, g_thetaT);
    cudaGetSymbolAddress((void**)&phiT,   g_phiT);
    cudaGetSymbolAddress((void**)&gg,     g_g);
    cudaGetSymbolAddress((void**)&attn,   g_attn);
    cudaGetSymbolAddress((void**)&oT,     g_oT);

    cudaFuncSetAttribute(mma_gemm<false>, cudaFuncAttributeMaxDynamicSharedMemorySize, SMEM_BYTES);
    cudaFuncSetAttribute(mma_gemm<true >, cudaFuncAttributeMaxDynamicSharedMemorySize, SMEM_BYTES);

    // 1) x -> xT  (tiled transpose)
    transpose_kernel<<<dim3(THW / 32, CC / 32, NB), dim3(32, 8)>>>(x, xT);

    // 2) xT -> xpT (pooled transpose)
    pooltrans_kernel<<<dim3(PP, NB), 256>>>(xT, xpT);

    // 3) thetaT = xT · w_theta^T : M=3136 N=512 K=1024
    mma_gemm<false><<<g128(THW, DD, NB), NT, SMEM_BYTES>>>(
        xT, w_theta, thetaT, THW, DD, CC,
        CC, CC, DD, (long long)THW * CC, 0LL, (long long)THW * DD,
        1.0f, nullptr, nullptr, nullptr, 0LL);

    // 4) phiT = xpT · w_phi^T : M=784 N=512 K=1024
    mma_gemm<false><<<g128(PP, DD, NB), NT, SMEM_BYTES>>>(
        xpT, w_phi, phiT, PP, DD, CC,
        CC, CC, DD, (long long)PP * CC, 0LL, (long long)PP * DD,
        1.0f, nullptr, nullptr, nullptr, 0LL);

    // 5) g = w_g · xp^T : M=512 N=784 K=1024  (output [D, PP], PP-contiguous)
    mma_gemm<false><<<g128(DD, PP, NB), NT, SMEM_BYTES>>>(
        w_g, xpT, gg, DD, PP, CC,
        CC, CC, PP, 0LL, (long long)PP * CC, (long long)DD * PP,
        1.0f, nullptr, nullptr, nullptr, 0LL);

    // 6) attn = thetaT · phiT^T * D^-0.5 : M=3136 N=784 K=512
    mma_gemm<false><<<g128(THW, PP, NB), NT, SMEM_BYTES>>>(
        thetaT, phiT, attn, THW, PP, DD,
        DD, DD, PP, (long long)THW * DD, (long long)PP * DD, (long long)THW * PP,
        0.044194173824159216f, nullptr, nullptr, nullptr, 0LL);

    // 7) softmax rows over 784
    softmax_kernel<<<(NB * THW + 7) / 8, 256>>>(attn, NB * THW, PP);

    // 8) oT = attn · g^T : M=3136 N=512 K=784
    mma_gemm<false><<<g128(THW, DD, NB), NT, SMEM_BYTES>>>(
        attn, gg, oT, THW, DD, PP,
        PP, PP, DD, (long long)THW * PP, (long long)DD * PP, (long long)THW * DD,
        1.0f, nullptr, nullptr, nullptr, 0LL);

    // 9) out = x + (w_out · oT^T)*scale + bias : M=1024 N=3136 K=512
    mma_gemm<true><<<g128(CC, THW, NB), NT, SMEM_BYTES>>>(
        w_out, oT, out, CC, THW, DD,
        DD, DD, THW, 0LL, (long long)THW * DD, (long long)CC * THW,
        1.0f, nscale, nbias, x, (long long)CC * THW);
}

// round 8
// speedup vs baseline: 3.0367x; 1.1795x over previous
#include <cuda_runtime.h>
#include <cstdint>
#include <math.h>

// ---------------------------------------------------------------------------
// Problem dims
// ---------------------------------------------------------------------------
#define NB   8
#define CC   1024
#define TT   16
#define HH   14
#define WW   14
#define DD   512
#define THW  (TT*HH*WW)   // 3136
#define PH   (HH/2)
#define PW   (WW/2)
#define PP   (TT*PH*PW)   // 784

// Scratch (all K-contiguous layouts; all GEMM inputs pre-rounded to tf32)
__device__ float g_xT    [NB*THW*CC];   // x^T (tf32)      [N, THW, C]
__device__ float g_xpT   [NB*PP*CC];    // pooled^T (tf32) [N, PP, C]
__device__ float g_thetaT[NB*THW*DD];   // theta^T (tf32)  [N, THW, D]
__device__ float g_phiT  [NB*PP*DD];    // phi^T (tf32)    [N, PP, D]
__device__ float g_g     [NB*DD*PP];    // g (tf32)        [N, D, PP]
__device__ float g_attn  [NB*THW*PP];   // logits/attn     [N, THW, PP]
__device__ float g_oT    [NB*THW*DD];   // o^T (tf32)      [N, THW, D]
__device__ float g_wth   [DD*CC];       // rounded weights
__device__ float g_wph   [DD*CC];
__device__ float g_wg    [DD*CC];
__device__ float g_wout  [CC*DD];

// ---------------------------------------------------------------------------
// Tile geometry: 128x128 CTA tile, BK=32, 128 threads (4 warps, 64x64 each)
// ---------------------------------------------------------------------------
#define BM  128
#define BN  128
#define BK  32
#define NT  128
#define PAD 4
#define LDT (BK + PAD)          // 36 floats = 144 B per row (16B-aligned)
#define TILE_FLOATS ((BM + BN) * LDT)
#define SMEM_BYTES  (2 * TILE_FLOATS * 4)   // 73728 B

// ---------------------------------------------------------------------------
// PTX helpers
// ---------------------------------------------------------------------------
__device__ __forceinline__ uint32_t tf32r(float f) {
    uint32_t u;
    asm("cvt.rna.tf32.f32 %0, %1;" : "=r"(u) : "f"(f));
    return u;
}
__device__ __forceinline__ float tf32f(float f) { return __uint_as_float(tf32r(f)); }
__device__ __forceinline__ uint32_t smem_u32(const void* p) {
    uint32_t a;
    asm("{ .reg .u64 t; cvta.to.shared.u64 t, %1; cvt.u32.u64 %0, t; }" : "=r"(a) : "l"(p));
    return a;
}
__device__ __forceinline__ void cp16(uint32_t dst, const void* src, bool pred) {
    int sz = pred ? 16 : 0;
    asm volatile("cp.async.ca.shared.global [%0], [%1], 16, %2;"
                 :: "r"(dst), "l"(src), "r"(sz));
}
#define CP_COMMIT() asm volatile("cp.async.commit_group;" ::: "memory")
template<int N> __device__ __forceinline__ void cp_wait() {
    asm volatile("cp.async.wait_group %0;" :: "n"(N) : "memory");
}
__device__ __forceinline__ void mma8(float* c, const uint32_t* a, const uint32_t* b) {
    asm volatile(
        "mma.sync.aligned.m16n8k8.row.col.f32.tf32.tf32.f32 "
        "{%0,%1,%2,%3}, {%4,%5,%6,%7}, {%8,%9}, {%0,%1,%2,%3};"
        : "+f"(c[0]), "+f"(c[1]), "+f"(c[2]), "+f"(c[3])
        : "r"(a[0]), "r"(a[1]), "r"(a[2]), "r"(a[3]), "r"(b[0]), "r"(b[1]));
}
__device__ __forceinline__ void ldsm4(uint32_t* r, uint32_t addr) {
    asm volatile("ldmatrix.sync.aligned.m8n8.x4.shared.b16 {%0,%1,%2,%3}, [%4];"
                 : "=r"(r[0]), "=r"(r[1]), "=r"(r[2]), "=r"(r[3]) : "r"(addr));
}

// K-contiguous staging: elem(r,k)=src[r*ld+k], cp.async 16B, zfill OOB.
__device__ __forceinline__ void stage_kc(const float* __restrict__ src, uint32_t tile_u,
                                         int rows, int k0, int K, long long ld, int tid) {
    #pragma unroll
    for (int i = 0; i < 8; i++) {
        int idx = tid + i * NT;
        int r   = idx >> 3;
        int c4  = (idx & 7) * 4;
        bool ok = (r < rows) && (k0 + c4 < K);
        const float* s = ok ? (src + (long long)r * ld + k0 + c4) : src;
        cp16(tile_u + (uint32_t)(r * LDT + c4) * 4u, s, ok);
    }
}

// ---------------------------------------------------------------------------
// tf32 mma.sync GEMM (ldmatrix fragments): C[M,N] = alpha * A·B^T, both KC.
// RND: round outputs to tf32 (feeding another GEMM). EPI: residual+affine.
// ---------------------------------------------------------------------------
template<bool EPI, bool RND>
__global__ __launch_bounds__(NT, 2)
void mma_gemm(const float* __restrict__ A, const float* __restrict__ B,
              float* __restrict__ C, int M, int N, int K,
              long long ldA, long long ldB, long long ldC,
              long long sA, long long sB, long long sC, float alpha,
              const float* __restrict__ scale, const float* __restrict__ bias,
              const float* __restrict__ resid, long long sR) {
    extern __shared__ float smem[];
    const int tid  = threadIdx.x;
    const int wid  = tid >> 5;
    const int lane = tid & 31;
    const int bz = blockIdx.z;
    const int bm = blockIdx.y * BM;
    const int bn = blockIdx.x * BN;

    A += (long long)bz * sA;
    B += (long long)bz * sB;
    C += (long long)bz * sC;

    const int rowsA = min(BM, M - bm);
    const int rowsB = min(BN, N - bn);
    const float* srcA = A + (long long)bm * ldA;
    const float* srcB = B + (long long)bn * ldB;

    const uint32_t smb = smem_u32(smem);
    const uint32_t uA[2] = { smb, smb + TILE_FLOATS * 4 };
    const uint32_t uB[2] = { smb + BM * LDT * 4, smb + (TILE_FLOATS + BM * LDT) * 4 };

    const int wm = (wid >> 1) * 64;
    const int wn = (wid & 1) * 64;

    // ldmatrix per-lane offsets (bytes), verified against mma quad layout:
    //   A x4 tiles: {rows+0,k0}, {rows+8,k0}, {rows+0,k+4}, {rows+8,k+4}
    //   B x4 tiles: {n+0,k0},   {n+0,k+4},  {n+8,k0},     {n+8,k+4}
    const int lrow = lane & 7, grp = lane >> 3;
    const uint32_t aoff = ((lrow + (grp & 1) * 8) * LDT + (grp >> 1) * 4) * 4u;
    const uint32_t boff = ((lrow + (grp >> 1) * 8) * LDT + (grp & 1) * 4) * 4u;

    float acc[4][8][4];
    #pragma unroll
    for (int i = 0; i < 4; i++)
        #pragma unroll
        for (int j = 0; j < 8; j++)
            #pragma unroll
            for (int e = 0; e < 4; e++) acc[i][j][e] = 0.f;

    const int KT = (K + BK - 1) / BK;

    // prologue
    stage_kc(srcA, uA[0], rowsA, 0, K, ldA, tid);
    stage_kc(srcB, uB[0], rowsB, 0, K, ldB, tid);
    CP_COMMIT();
    cp_wait<0>();
    __syncthreads();

    for (int kt = 0; kt < KT; kt++) {
        const int buf = kt & 1;
        const bool pf = (kt + 1 < KT);
        if (pf) {
            const int k0 = (kt + 1) * BK;
            stage_kc(srcA, uA[buf ^ 1], rowsA, k0, K, ldA, tid);
            stage_kc(srcB, uB[buf ^ 1], rowsB, k0, K, ldB, tid);
            CP_COMMIT();
        }

        const uint32_t abase = uA[buf] + (uint32_t)(wm * LDT) * 4u + aoff;
        const uint32_t bbase = uB[buf] + (uint32_t)(wn * LDT) * 4u + boff;
        #pragma unroll
        for (int ks = 0; ks < 4; ks++) {
            const uint32_t ksb = (uint32_t)(ks * 8) * 4u;
            uint32_t afr[4][4], bfr[8][2];
            #pragma unroll
            for (int i = 0; i < 4; i++)
                ldsm4(afr[i], abase + (uint32_t)(i * 16 * LDT) * 4u + ksb);
            #pragma unroll
            for (int p = 0; p < 4; p++) {
                uint32_t bq[4];
                ldsm4(bq, bbase + (uint32_t)(p * 16 * LDT) * 4u + ksb);
                bfr[2 * p][0] = bq[0]; bfr[2 * p][1] = bq[1];
                bfr[2 * p + 1][0] = bq[2]; bfr[2 * p + 1][1] = bq[3];
            }
            #pragma unroll
            for (int i = 0; i < 4; i++)
                #pragma unroll
                for (int j = 0; j < 8; j++)
                    mma8(acc[i][j], afr[i], bfr[j]);
        }

        if (pf) cp_wait<0>();
        __syncthreads();
    }

    // epilogue
    #pragma unroll
    for (int i = 0; i < 4; i++) {
        const int r0 = bm + wm + i * 16 + (lane >> 2);
        #pragma unroll
        for (int j = 0; j < 8; j++) {
            const int c = bn + wn + j * 8 + 2 * (lane & 3);
            if (c >= N) continue;
            #pragma unroll
            for (int h = 0; h < 2; h++) {
                const int r = r0 + h * 8;
                if (r >= M) continue;
                const long long base = (long long)r * ldC + c;
                float2 o;
                if (EPI) {
                    const float sc = scale[r], bi = bias[r];
                    const float2 rr = *reinterpret_cast<const float2*>(
                        &resid[(long long)bz * sR + base]);
                    o.x = rr.x + fmaf(acc[i][j][2 * h + 0], sc, bi);
                    o.y = rr.y + fmaf(acc[i][j][2 * h + 1], sc, bi);
                } else {
                    o.x = alpha * acc[i][j][2 * h + 0];
                    o.y = alpha * acc[i][j][2 * h + 1];
                    if (RND) { o.x = tf32f(o.x); o.y = tf32f(o.y); }
                }
                *reinterpret_cast<float2*>(&C[base]) = o;
            }
        }
    }
}

// ---------------------------------------------------------------------------
// Weight rounding: dst = tf32(src)
// ---------------------------------------------------------------------------
__global__ void round_kernel(const float* __restrict__ src, float* __restrict__ dst,
                             int n) {
    int i = (blockIdx.x * blockDim.x + threadIdx.x) * 4;
    if (i >= n) return;
    float4 v = *reinterpret_cast<const float4*>(src + i);
    float4 o;
    o.x = tf32f(v.x); o.y = tf32f(v.y); o.z = tf32f(v.z); o.w = tf32f(v.w);
    *reinterpret_cast<float4*>(dst + i) = o;
}

// ---------------------------------------------------------------------------
// Tiled transpose + tf32 round: x [C, THW] -> xT [THW, C]
// ---------------------------------------------------------------------------
__global__ void transpose_kernel(const float* __restrict__ x, float* __restrict__ xT) {
    __shared__ float tile[32][33];
    const int bz = blockIdx.z;
    const float* src = x  + (long long)bz * CC * THW;
    float*       dst = xT + (long long)bz * THW * CC;
    const int t0 = blockIdx.x * 32;
    const int c0 = blockIdx.y * 32;
    #pragma unroll
    for (int j = threadIdx.y; j < 32; j += 8)
        tile[j][threadIdx.x] = tf32f(src[(long long)(c0 + j) * THW + t0 + threadIdx.x]);
    __syncthreads();
    #pragma unroll
    for (int j = threadIdx.y; j < 32; j += 8)
        dst[(long long)(t0 + j) * CC + c0 + threadIdx.x] = tile[threadIdx.x][j];
}

// ---------------------------------------------------------------------------
// Pooled transpose: xT [THW, C] -> xpT [PP, C] (inputs already tf32; max of
// rounded == rounded max since cvt.rna is monotone)
// ---------------------------------------------------------------------------
__global__ void pooltrans_kernel(const float* __restrict__ xT, float* __restrict__ xpT) {
    const int p  = blockIdx.x;
    const int nb = blockIdx.y;
    const int t  = p / (PH * PW);
    const int ij = p % (PH * PW);
    const int i  = ij / PW;
    const int j  = ij % PW;
    const int r00 = t * (HH * WW) + (2 * i) * WW + 2 * j;
    const float4* s0 = (const float4*)(xT + ((long long)nb * THW + r00) * CC);
    const float4* s1 = s0 + CC / 4;
    const float4* s2 = (const float4*)(xT + ((long long)nb * THW + r00 + WW) * CC);
    const float4* s3 = s2 + CC / 4;
    float4* d = (float4*)(xpT + ((long long)nb * PP + p) * CC);
    const int c = threadIdx.x;
    float4 a = s0[c], b = s1[c], e = s2[c], f = s3[c];
    float4 o;
    o.x = fmaxf(fmaxf(a.x, b.x), fmaxf(e.x, f.x));
    o.y = fmaxf(fmaxf(a.y, b.y), fmaxf(e.y, f.y));
    o.z = fmaxf(fmaxf(a.z, b.z), fmaxf(e.z, f.z));
    o.w = fmaxf(fmaxf(a.w, b.w), fmaxf(e.w, f.w));
    d[c] = o;
}

// ---------------------------------------------------------------------------
// Warp-per-row softmax (cols = 784); output rounded to tf32 (feeds GEMM)
// ---------------------------------------------------------------------------
__global__ void softmax_kernel(float* __restrict__ data, int rows, int cols) {
    int warp = blockIdx.x * (blockDim.x >> 5) + (threadIdx.x >> 5);
    if (warp >= rows) return;
    int lane = threadIdx.x & 31;
    float* row = data + (long long)warp * cols;
    float vals[25];
    int cnt = 0;
    float mx = -INFINITY;
    for (int c = lane; c < cols; c += 32) {
        float v = row[c];
        vals[cnt++] = v;
        mx = fmaxf(mx, v);
    }
    #pragma unroll
    for (int o = 16; o; o >>= 1) mx = fmaxf(mx, __shfl_xor_sync(0xffffffffu, mx, o));
    float sum = 0.f;
    for (int i = 0; i < cnt; i++) { vals[i] = __expf(vals[i] - mx); sum += vals[i]; }
    #pragma unroll
    for (int o = 16; o; o >>= 1) sum += __shfl_xor_sync(0xffffffffu, sum, o);
    float inv = 1.0f / sum;
    cnt = 0;
    for (int c = lane; c < cols; c += 32) row[c] = tf32f(vals[cnt++] * inv);
}

// ---------------------------------------------------------------------------
// Launch
// ---------------------------------------------------------------------------
static inline dim3 g128(int M, int N, int b) {
    return dim3((N + BN - 1) / BN, (M + BM - 1) / BM, b);
}

extern "C" void kernel_launch(void* const* d_in, const int* in_sizes, int n_in,
                              void* d_out, int out_size) {
    const float* x       = (const float*)d_in[0];
    const float* w_theta = (const float*)d_in[1];
    const float* w_phi   = (const float*)d_in[2];
    const float* w_g     = (const float*)d_in[3];
    const float* w_out   = (const float*)d_in[4];
    const float* nscale  = (const float*)d_in[5];
    const float* nbias   = (const float*)d_in[6];
    float* out = (float*)d_out;

    float *xT, *xpT, *thetaT, *phiT, *gg, *attn, *oT, *wth, *wph, *wg, *wout;
    cudaGetSymbolAddress((void**)&xT,     g_xT);
    cudaGetSymbolAddress((void**)&xpT,    g_xpT);
    cudaGetSymbolAddress((void**)&thetaT, g_thetaT);
    cudaGetSymbolAddress((void**)&phiT,   g_phiT);
    cudaGetSymbolAddress((void**)&gg,     g_g);
    cudaGetSymbolAddress((void**)&attn,   g_attn);
    cudaGetSymbolAddress((void**)&oT,     g_oT);
    cudaGetSymbolAddress((void**)&wth,    g_wth);
    cudaGetSymbolAddress((void**)&wph,    g_wph);
    cudaGetSymbolAddress((void**)&wg,     g_wg);
    cudaGetSymbolAddress((void**)&wout,   g_wout);

    cudaFuncSetAttribute(mma_gemm<false, true >, cudaFuncAttributeMaxDynamicSharedMemorySize, SMEM_BYTES);
    cudaFuncSetAttribute(mma_gemm<false, false>, cudaFuncAttributeMaxDynamicSharedMemorySize, SMEM_BYTES);
    cudaFuncSetAttribute(mma_gemm<true,  false>, cudaFuncAttributeMaxDynamicSharedMemorySize, SMEM_BYTES);

    // 0) round weights to tf32 (once per launch; tiny)
    round_kernel<<<(DD * CC / 4 + 255) / 256, 256>>>(w_theta, wth, DD * CC);
    round_kernel<<<(DD * CC / 4 + 255) / 256, 256>>>(w_phi,   wph, DD * CC);
    round_kernel<<<(DD * CC / 4 + 255) / 256, 256>>>(w_g,     wg,  DD * CC);
    round_kernel<<<(CC * DD / 4 + 255) / 256, 256>>>(w_out,   wout, CC * DD);

    // 1) x -> xT (transpose + round)
    transpose_kernel<<<dim3(THW / 32, CC / 32, NB), dim3(32, 8)>>>(x, xT);

    // 2) xT -> xpT (pooled transpose)
    pooltrans_kernel<<<dim3(PP, NB), 256>>>(xT, xpT);

    // 3) thetaT = xT · wth^T : M=3136 N=512 K=1024  (round out)
    mma_gemm<false, true><<<g128(THW, DD, NB), NT, SMEM_BYTES>>>(
        xT, wth, thetaT, THW, DD, CC,
        CC, CC, DD, (long long)THW * CC, 0LL, (long long)THW * DD,
        1.0f, nullptr, nullptr, nullptr, 0LL);

    // 4) phiT = xpT · wph^T : M=784 N=512 K=1024  (round out)
    mma_gemm<false, true><<<g128(PP, DD, NB), NT, SMEM_BYTES>>>(
        xpT, wph, phiT, PP, DD, CC,
        CC, CC, DD, (long long)PP * CC, 0LL, (long long)PP * DD,
        1.0f, nullptr, nullptr, nullptr, 0LL);

    // 5) g = wg · xpT^T : M=512 N=784 K=1024  (round out)
    mma_gemm<false, true><<<g128(DD, PP, NB), NT, SMEM_BYTES>>>(
        wg, xpT, gg, DD, PP, CC,
        CC, CC, PP, 0LL, (long long)PP * CC, (long long)DD * PP,
        1.0f, nullptr, nullptr, nullptr, 0LL);

    // 6) attn = thetaT · phiT^T * D^-0.5 : M=3136 N=784 K=512  (softmax rounds)
    mma_gemm<false, false><<<g128(THW, PP, NB), NT, SMEM_BYTES>>>(
        thetaT, phiT, attn, THW, PP, DD,
        DD, DD, PP, (long long)THW * DD, (long long)PP * DD, (long long)THW * PP,
        0.044194173824159216f, nullptr, nullptr, nullptr, 0LL);

    // 7) softmax rows over 784 (rounds output)
    softmax_kernel<<<(NB * THW + 7) / 8, 256>>>(attn, NB * THW, PP);

    // 8) oT = attn · g^T : M=3136 N=512 K=784  (round out)
    mma_gemm<false, true><<<g128(THW, DD, NB), NT, SMEM_BYTES>>>(
        attn, gg, oT, THW, DD, PP,
        PP, PP, DD, (long long)THW * PP, (long long)DD * PP, (long long)THW * DD,
        1.0f, nullptr, nullptr, nullptr, 0LL);

    // 9) out = x + (wout · oT^T)*scale + bias : M=1024 N=3136 K=512
    mma_gemm<true, false><<<g128(CC, THW, NB), NT, SMEM_BYTES>>>(
        wout, oT, out, CC, THW, DD,
        DD, DD, THW, 0LL, (long long)THW * DD, (long long)CC * THW,
        1.0f, nscale, nbias, x, (long long)CC * THW);
}

// round 9
// speedup vs baseline: 3.3664x; 1.1086x over previous
#include <cuda_runtime.h>
#include <cstdint>
#include <math.h>

// ---------------------------------------------------------------------------
// Problem dims
// ---------------------------------------------------------------------------
#define NB   8
#define CC   1024
#define TT   16
#define HH   14
#define WW   14
#define DD   512
#define THW  (TT*HH*WW)   // 3136
#define PH   (HH/2)
#define PW   (WW/2)
#define PP   (TT*PH*PW)   // 784

// Scratch (all K-contiguous layouts; all GEMM inputs pre-rounded to tf32)
__device__ float g_xT    [NB*THW*CC];
__device__ float g_xpT   [NB*PP*CC];
__device__ float g_thetaT[NB*THW*DD];
__device__ float g_phiT  [NB*PP*DD];
__device__ float g_g     [NB*DD*PP];
__device__ float g_attn  [NB*THW*PP];
__device__ float g_oT    [NB*THW*DD];
__device__ float g_wth   [DD*CC];
__device__ float g_wph   [DD*CC];
__device__ float g_wg    [DD*CC];
__device__ float g_wout  [CC*DD];

// ---------------------------------------------------------------------------
// Tile geometry: 128x128 CTA tile, BK=32, 256 threads (8 warps, 64x32 each)
// ---------------------------------------------------------------------------
#define BM  128
#define BN  128
#define BK  32
#define NT  256
#define PAD 4
#define LDT (BK + PAD)          // 36 floats = 144 B per row (16B-aligned)
#define TILE_FLOATS ((BM + BN) * LDT)
#define SMEM_BYTES  (2 * TILE_FLOATS * 4)   // 73728 B

// ---------------------------------------------------------------------------
// PTX helpers
// ---------------------------------------------------------------------------
__device__ __forceinline__ uint32_t tf32r(float f) {
    uint32_t u;
    asm("cvt.rna.tf32.f32 %0, %1;" : "=r"(u) : "f"(f));
    return u;
}
__device__ __forceinline__ float tf32f(float f) { return __uint_as_float(tf32r(f)); }
__device__ __forceinline__ uint32_t smem_u32(const void* p) {
    uint32_t a;
    asm("{ .reg .u64 t; cvta.to.shared.u64 t, %1; cvt.u32.u64 %0, t; }" : "=r"(a) : "l"(p));
    return a;
}
__device__ __forceinline__ void cp16(uint32_t dst, const void* src, bool pred) {
    int sz = pred ? 16 : 0;
    asm volatile("cp.async.ca.shared.global [%0], [%1], 16, %2;"
                 :: "r"(dst), "l"(src), "r"(sz));
}
#define CP_COMMIT() asm volatile("cp.async.commit_group;" ::: "memory")
template<int N> __device__ __forceinline__ void cp_wait() {
    asm volatile("cp.async.wait_group %0;" :: "n"(N) : "memory");
}
__device__ __forceinline__ void mma8(float* c, const uint32_t* a, const uint32_t* b) {
    asm volatile(
        "mma.sync.aligned.m16n8k8.row.col.f32.tf32.tf32.f32 "
        "{%0,%1,%2,%3}, {%4,%5,%6,%7}, {%8,%9}, {%0,%1,%2,%3};"
        : "+f"(c[0]), "+f"(c[1]), "+f"(c[2]), "+f"(c[3])
        : "r"(a[0]), "r"(a[1]), "r"(a[2]), "r"(a[3]), "r"(b[0]), "r"(b[1]));
}
__device__ __forceinline__ void ldsm4(uint32_t* r, uint32_t addr) {
    asm volatile("ldmatrix.sync.aligned.m8n8.x4.shared.b16 {%0,%1,%2,%3}, [%4];"
                 : "=r"(r[0]), "=r"(r[1]), "=r"(r[2]), "=r"(r[3]) : "r"(addr));
}

// K-contiguous staging: elem(r,k)=src[r*ld+k], cp.async 16B, zfill OOB.
// 256 threads x 4 iters = 1024 x 16B chunks = 128 rows x 32 k.
__device__ __forceinline__ void stage_kc(const float* __restrict__ src, uint32_t tile_u,
                                         int rows, int k0, int K, long long ld, int tid) {
    #pragma unroll
    for (int i = 0; i < 4; i++) {
        int idx = tid + i * NT;
        int r   = idx >> 3;
        int c4  = (idx & 7) * 4;
        bool ok = (r < rows) && (k0 + c4 < K);
        const float* s = ok ? (src + (long long)r * ld + k0 + c4) : src;
        cp16(tile_u + (uint32_t)(r * LDT + c4) * 4u, s, ok);
    }
}

// ---------------------------------------------------------------------------
// tf32 mma.sync GEMM (ldmatrix fragments): C[M,N] = alpha * A·B^T, both KC.
// 8 warps, 64x32 warp tile (2x4 warp grid), double-buffered cp.async smem.
// RND: round outputs to tf32. EPI: residual+affine.
// ---------------------------------------------------------------------------
template<bool EPI, bool RND>
__global__ __launch_bounds__(NT, 2)
void mma_gemm(const float* __restrict__ A, const float* __restrict__ B,
              float* __restrict__ C, int M, int N, int K,
              long long ldA, long long ldB, long long ldC,
              long long sA, long long sB, long long sC, float alpha,
              const float* __restrict__ scale, const float* __restrict__ bias,
              const float* __restrict__ resid, long long sR) {
    extern __shared__ float smem[];
    const int tid  = threadIdx.x;
    const int wid  = tid >> 5;
    const int lane = tid & 31;
    const int bz = blockIdx.z;
    const int bm = blockIdx.y * BM;
    const int bn = blockIdx.x * BN;

    A += (long long)bz * sA;
    B += (long long)bz * sB;
    C += (long long)bz * sC;

    const int rowsA = min(BM, M - bm);
    const int rowsB = min(BN, N - bn);
    const float* srcA = A + (long long)bm * ldA;
    const float* srcB = B + (long long)bn * ldB;

    const uint32_t smb = smem_u32(smem);
    const uint32_t uA[2] = { smb, smb + TILE_FLOATS * 4 };
    const uint32_t uB[2] = { smb + BM * LDT * 4, smb + (TILE_FLOATS + BM * LDT) * 4 };

    const int wm = (wid >> 2) * 64;   // 2 warp rows
    const int wn = (wid & 3) * 32;    // 4 warp cols

    // ldmatrix per-lane offsets (bytes):
    //   A x4 tiles: {rows+0,k0}, {rows+8,k0}, {rows+0,k+4}, {rows+8,k+4}
    //   B x4 tiles: {n+0,k0},   {n+0,k+4},  {n+8,k0},     {n+8,k+4}
    const int lrow = lane & 7, grp = lane >> 3;
    const uint32_t aoff = ((lrow + (grp & 1) * 8) * LDT + (grp >> 1) * 4) * 4u;
    const uint32_t boff = ((lrow + (grp >> 1) * 8) * LDT + (grp & 1) * 4) * 4u;

    float acc[4][4][4];
    #pragma unroll
    for (int i = 0; i < 4; i++)
        #pragma unroll
        for (int j = 0; j < 4; j++)
            #pragma unroll
            for (int e = 0; e < 4; e++) acc[i][j][e] = 0.f;

    const int KT = (K + BK - 1) / BK;

    // prologue
    stage_kc(srcA, uA[0], rowsA, 0, K, ldA, tid);
    stage_kc(srcB, uB[0], rowsB, 0, K, ldB, tid);
    CP_COMMIT();
    cp_wait<0>();
    __syncthreads();

    for (int kt = 0; kt < KT; kt++) {
        const int buf = kt & 1;
        const bool pf = (kt + 1 < KT);
        if (pf) {
            const int k0 = (kt + 1) * BK;
            stage_kc(srcA, uA[buf ^ 1], rowsA, k0, K, ldA, tid);
            stage_kc(srcB, uB[buf ^ 1], rowsB, k0, K, ldB, tid);
            CP_COMMIT();
        }

        const uint32_t abase = uA[buf] + (uint32_t)(wm * LDT) * 4u + aoff;
        const uint32_t bbase = uB[buf] + (uint32_t)(wn * LDT) * 4u + boff;
        #pragma unroll
        for (int ks = 0; ks < 4; ks++) {
            const uint32_t ksb = (uint32_t)(ks * 8) * 4u;
            uint32_t afr[4][4], bfr[4][2];
            #pragma unroll
            for (int i = 0; i < 4; i++)
                ldsm4(afr[i], abase + (uint32_t)(i * 16 * LDT) * 4u + ksb);
            #pragma unroll
            for (int p = 0; p < 2; p++) {
                uint32_t bq[4];
                ldsm4(bq, bbase + (uint32_t)(p * 16 * LDT) * 4u + ksb);
                bfr[2 * p][0] = bq[0]; bfr[2 * p][1] = bq[1];
                bfr[2 * p + 1][0] = bq[2]; bfr[2 * p + 1][1] = bq[3];
            }
            #pragma unroll
            for (int i = 0; i < 4; i++)
                #pragma unroll
                for (int j = 0; j < 4; j++)
                    mma8(acc[i][j], afr[i], bfr[j]);
        }

        if (pf) cp_wait<0>();
        __syncthreads();
    }

    // epilogue
    #pragma unroll
    for (int i = 0; i < 4; i++) {
        const int r0 = bm + wm + i * 16 + (lane >> 2);
        #pragma unroll
        for (int j = 0; j < 4; j++) {
            const int c = bn + wn + j * 8 + 2 * (lane & 3);
            if (c >= N) continue;
            #pragma unroll
            for (int h = 0; h < 2; h++) {
                const int r = r0 + h * 8;
                if (r >= M) continue;
                const long long base = (long long)r * ldC + c;
                float2 o;
                if (EPI) {
                    const float sc = scale[r], bi = bias[r];
                    const float2 rr = *reinterpret_cast<const float2*>(
                        &resid[(long long)bz * sR + base]);
                    o.x = rr.x + fmaf(acc[i][j][2 * h + 0], sc, bi);
                    o.y = rr.y + fmaf(acc[i][j][2 * h + 1], sc, bi);
                } else {
                    o.x = alpha * acc[i][j][2 * h + 0];
                    o.y = alpha * acc[i][j][2 * h + 1];
                    if (RND) { o.x = tf32f(o.x); o.y = tf32f(o.y); }
                }
                *reinterpret_cast<float2*>(&C[base]) = o;
            }
        }
    }
}

// ---------------------------------------------------------------------------
// Fused weight rounding: all four weight arrays are 512*1024 elements.
// ---------------------------------------------------------------------------
#define WELEMS (DD*CC)
__global__ void round4_kernel(const float* __restrict__ s0, float* __restrict__ d0,
                              const float* __restrict__ s1, float* __restrict__ d1,
                              const float* __restrict__ s2, float* __restrict__ d2,
                              const float* __restrict__ s3, float* __restrict__ d3) {
    int gi = (blockIdx.x * blockDim.x + threadIdx.x) * 4;
    int arr = gi / WELEMS;
    int i   = gi % WELEMS;
    const float* src = (arr == 0) ? s0 : (arr == 1) ? s1 : (arr == 2) ? s2 : s3;
    float*       dst = (arr == 0) ? d0 : (arr == 1) ? d1 : (arr == 2) ? d2 : d3;
    float4 v = *reinterpret_cast<const float4*>(src + i);
    float4 o;
    o.x = tf32f(v.x); o.y = tf32f(v.y); o.z = tf32f(v.z); o.w = tf32f(v.w);
    *reinterpret_cast<float4*>(dst + i) = o;
}

// ---------------------------------------------------------------------------
// Tiled transpose + tf32 round: x [C, THW] -> xT [THW, C]
// ---------------------------------------------------------------------------
__global__ void transpose_kernel(const float* __restrict__ x, float* __restrict__ xT) {
    __shared__ float tile[32][33];
    const int bz = blockIdx.z;
    const float* src = x  + (long long)bz * CC * THW;
    float*       dst = xT + (long long)bz * THW * CC;
    const int t0 = blockIdx.x * 32;
    const int c0 = blockIdx.y * 32;
    #pragma unroll
    for (int j = threadIdx.y; j < 32; j += 8)
        tile[j][threadIdx.x] = tf32f(src[(long long)(c0 + j) * THW + t0 + threadIdx.x]);
    __syncthreads();
    #pragma unroll
    for (int j = threadIdx.y; j < 32; j += 8)
        dst[(long long)(t0 + j) * CC + c0 + threadIdx.x] = tile[threadIdx.x][j];
}

// ---------------------------------------------------------------------------
// Pooled transpose: xT [THW, C] -> xpT [PP, C]
// ---------------------------------------------------------------------------
__global__ void pooltrans_kernel(const float* __restrict__ xT, float* __restrict__ xpT) {
    const int p  = blockIdx.x;
    const int nb = blockIdx.y;
    const int t  = p / (PH * PW);
    const int ij = p % (PH * PW);
    const int i  = ij / PW;
    const int j  = ij % PW;
    const int r00 = t * (HH * WW) + (2 * i) * WW + 2 * j;
    const float4* s0 = (const float4*)(xT + ((long long)nb * THW + r00) * CC);
    const float4* s1 = s0 + CC / 4;
    const float4* s2 = (const float4*)(xT + ((long long)nb * THW + r00 + WW) * CC);
    const float4* s3 = s2 + CC / 4;
    float4* d = (float4*)(xpT + ((long long)nb * PP + p) * CC);
    const int c = threadIdx.x;
    float4 a = s0[c], b = s1[c], e = s2[c], f = s3[c];
    float4 o;
    o.x = fmaxf(fmaxf(a.x, b.x), fmaxf(e.x, f.x));
    o.y = fmaxf(fmaxf(a.y, b.y), fmaxf(e.y, f.y));
    o.z = fmaxf(fmaxf(a.z, b.z), fmaxf(e.z, f.z));
    o.w = fmaxf(fmaxf(a.w, b.w), fmaxf(e.w, f.w));
    d[c] = o;
}

// ---------------------------------------------------------------------------
// Warp-per-row softmax (cols = 784); output rounded to tf32
// ---------------------------------------------------------------------------
__global__ void softmax_kernel(float* __restrict__ data, int rows, int cols) {
    int warp = blockIdx.x * (blockDim.x >> 5) + (threadIdx.x >> 5);
    if (warp >= rows) return;
    int lane = threadIdx.x & 31;
    float* row = data + (long long)warp * cols;
    float vals[25];
    int cnt = 0;
    float mx = -INFINITY;
    for (int c = lane; c < cols; c += 32) {
        float v = row[c];
        vals[cnt++] = v;
        mx = fmaxf(mx, v);
    }
    #pragma unroll
    for (int o = 16; o; o >>= 1) mx = fmaxf(mx, __shfl_xor_sync(0xffffffffu, mx, o));
    float sum = 0.f;
    for (int i = 0; i < cnt; i++) { vals[i] = __expf(vals[i] - mx); sum += vals[i]; }
    #pragma unroll
    for (int o = 16; o; o >>= 1) sum += __shfl_xor_sync(0xffffffffu, sum, o);
    float inv = 1.0f / sum;
    cnt = 0;
    for (int c = lane; c < cols; c += 32) row[c] = tf32f(vals[cnt++] * inv);
}

// ---------------------------------------------------------------------------
// Launch
// ---------------------------------------------------------------------------
static inline dim3 g128(int M, int N, int b) {
    return dim3((N + BN - 1) / BN, (M + BM - 1) / BM, b);
}

extern "C" void kernel_launch(void* const* d_in, const int* in_sizes, int n_in,
                              void* d_out, int out_size) {
    const float* x       = (const float*)d_in[0];
    const float* w_theta = (const float*)d_in[1];
    const float* w_phi   = (const float*)d_in[2];
    const float* w_g     = (const float*)d_in[3];
    const float* w_out   = (const float*)d_in[4];
    const float* nscale  = (const float*)d_in[5];
    const float* nbias   = (const float*)d_in[6];
    float* out = (float*)d_out;

    float *xT, *xpT, *thetaT, *phiT, *gg, *attn, *oT, *wth, *wph, *wg, *wout;
    cudaGetSymbolAddress((void**)&xT,     g_xT);
    cudaGetSymbolAddress((void**)&xpT,    g_xpT);
    cudaGetSymbolAddress((void**)&thetaT, g_thetaT);
    cudaGetSymbolAddress((void**)&phiT,   g_phiT);
    cudaGetSymbolAddress((void**)&gg,     g_g);
    cudaGetSymbolAddress((void**)&attn,   g_attn);
    cudaGetSymbolAddress((void**)&oT,     g_oT);
    cudaGetSymbolAddress((void**)&wth,    g_wth);
    cudaGetSymbolAddress((void**)&wph,    g_wph);
    cudaGetSymbolAddress((void**)&wg,     g_wg);
    cudaGetSymbolAddress((void**)&wout,   g_wout);

    cudaFuncSetAttribute(mma_gemm<false, true >, cudaFuncAttributeMaxDynamicSharedMemorySize, SMEM_BYTES);
    cudaFuncSetAttribute(mma_gemm<false, false>, cudaFuncAttributeMaxDynamicSharedMemorySize, SMEM_BYTES);
    cudaFuncSetAttribute(mma_gemm<true,  false>, cudaFuncAttributeMaxDynamicSharedMemorySize, SMEM_BYTES);

    // 0) round all weights (one launch)
    round4_kernel<<<(4 * WELEMS / 4 + 255) / 256, 256>>>(
        w_theta, wth, w_phi, wph, w_g, wg, w_out, wout);

    // 1) x -> xT (transpose + round)
    transpose_kernel<<<dim3(THW / 32, CC / 32, NB), dim3(32, 8)>>>(x, xT);

    // 2) xT -> xpT (pooled transpose)
    pooltrans_kernel<<<dim3(PP, NB), 256>>>(xT, xpT);

    // 3) thetaT = xT · wth^T : M=3136 N=512 K=1024  (round out)
    mma_gemm<false, true><<<g128(THW, DD, NB), NT, SMEM_BYTES>>>(
        xT, wth, thetaT, THW, DD, CC,
        CC, CC, DD, (long long)THW * CC, 0LL, (long long)THW * DD,
        1.0f, nullptr, nullptr, nullptr, 0LL);

    // 4) phiT = xpT · wph^T : M=784 N=512 K=1024  (round out)
    mma_gemm<false, true><<<g128(PP, DD, NB), NT, SMEM_BYTES>>>(
        xpT, wph, phiT, PP, DD, CC,
        CC, CC, DD, (long long)PP * CC, 0LL, (long long)PP * DD,
        1.0f, nullptr, nullptr, nullptr, 0LL);

    // 5) g = wg · xpT^T : M=512 N=784 K=1024  (round out)
    mma_gemm<false, true><<<g128(DD, PP, NB), NT, SMEM_BYTES>>>(
        wg, xpT, gg, DD, PP, CC,
        CC, CC, PP, 0LL, (long long)PP * CC, (long long)DD * PP,
        1.0f, nullptr, nullptr, nullptr, 0LL);

    // 6) attn = thetaT · phiT^T * D^-0.5 : M=3136 N=784 K=512
    mma_gemm<false, false><<<g128(THW, PP, NB), NT, SMEM_BYTES>>>(
        thetaT, phiT, attn, THW, PP, DD,
        DD, DD, PP, (long long)THW * DD, (long long)PP * DD, (long long)THW * PP,
        0.044194173824159216f, nullptr, nullptr, nullptr, 0LL);

    // 7) softmax rows over 784 (rounds output)
    softmax_kernel<<<(NB * THW + 7) / 8, 256>>>(attn, NB * THW, PP);

    // 8) oT = attn · g^T : M=3136 N=512 K=784  (round out)
    mma_gemm<false, true><<<g128(THW, DD, NB), NT, SMEM_BYTES>>>(
        attn, gg, oT, THW, DD, PP,
        PP, PP, DD, (long long)THW * PP, (long long)DD * PP, (long long)THW * DD,
        1.0f, nullptr, nullptr, nullptr, 0LL);

    // 9) out = x + (wout · oT^T)*scale + bias : M=1024 N=3136 K=512
    mma_gemm<true, false><<<g128(CC, THW, NB), NT, SMEM_BYTES>>>(
        wout, oT, out, CC, THW, DD,
        DD, DD, THW, 0LL, (long long)THW * DD, (long long)CC * THW,
        1.0f, nscale, nbias, x, (long long)CC * THW);
}